// round 3
// baseline (speedup 1.0000x reference)
#include <cuda_runtime.h>
#include <math.h>

#define H      1024
#define NHD    8
#define DFF    4096
#define PLIN   256
#define CTX    2048
#define MAXHD  512
#define NL     15

// ---------------- device scratch (no allocations allowed) ----------------
__device__ float g_h[H];
__device__ float g_hs[H];
__device__ float g_qkv[10 * MAXHD];      // q (8*hd) | k (hd) | v (hd) accumulators
__device__ float g_qf[NHD * MAXHD];
__device__ float g_kf[MAXHD];
__device__ float g_vf[MAXHD];
__device__ float g_scores[NHD * CTX];
__device__ float g_prob[NHD * CTX];
__device__ float g_x[NHD * MAXHD];       // attn output (dense h*hd+d)
__device__ float g_o[H];
__device__ float g_gu[2 * DFF];          // gate | up accumulators
__device__ float g_mlp[H];
__device__ float g_pg[PLIN];
__device__ float g_g2[H];
__device__ float g_ksave[2][MAXHD];
__device__ float g_vsave[2][MAXHD];

// ---------------- helpers ----------------
__device__ __forceinline__ float gelu_tanh(float x) {
    float x3 = x * x * x;
    return 0.5f * x * (1.f + tanhf(0.7978845608028654f * (x + 0.044715f * x3)));
}

__device__ float blockSum(float v) {
    __shared__ float red[32];
    int lane = threadIdx.x & 31, wid = threadIdx.x >> 5, nw = blockDim.x >> 5;
    __syncthreads();
    #pragma unroll
    for (int o = 16; o; o >>= 1) v += __shfl_down_sync(0xffffffffu, v, o);
    if (lane == 0) red[wid] = v;
    __syncthreads();
    float s = (threadIdx.x < nw) ? red[threadIdx.x] : 0.f;
    if (wid == 0) {
        #pragma unroll
        for (int o = 16; o; o >>= 1) s += __shfl_down_sync(0xffffffffu, s, o);
        if (lane == 0) red[0] = s;
    }
    __syncthreads();
    return red[0];
}

__device__ float blockMax(float v) {
    __shared__ float red[32];
    int lane = threadIdx.x & 31, wid = threadIdx.x >> 5, nw = blockDim.x >> 5;
    __syncthreads();
    #pragma unroll
    for (int o = 16; o; o >>= 1) v = fmaxf(v, __shfl_down_sync(0xffffffffu, v, o));
    if (lane == 0) red[wid] = v;
    __syncthreads();
    float s = (threadIdx.x < nw) ? red[threadIdx.x] : -1e30f;
    if (wid == 0) {
        #pragma unroll
        for (int o = 16; o; o >>= 1) s = fmaxf(s, __shfl_down_sync(0xffffffffu, s, o));
        if (lane == 0) red[0] = s;
    }
    __syncthreads();
    return red[0];
}

// ---------------- kernels ----------------

// embed lookup + layer-0 input rmsnorm + zero all accumulators
__global__ void k_init(const float* __restrict__ embed, const float* __restrict__ img,
                       const int* __restrict__ ids, const float* __restrict__ ln_in0) {
    int t = threadIdx.x;
    float a = fabsf(img[t]);
    float asum = blockSum(a);
    float is = (asum > 0.f) ? 1.f : 0.f;
    float hv = embed[(size_t)ids[0] * H + t] * 32.0f * (1.f - is) + img[t] * is;
    g_h[t] = hv;
    float ss = blockSum(hv * hv);
    float sc = rsqrtf(ss / (float)H + 1e-6f);
    g_hs[t] = hv * sc * (1.f + ln_in0[t]);
    for (int i = t; i < 10 * MAXHD; i += 1024) g_qkv[i] = 0.f;
    for (int i = t; i < NHD * MAXHD; i += 1024) g_x[i] = 0.f;
    g_o[t] = 0.f;
    for (int i = t; i < 2 * DFF; i += 1024) g_gu[i] = 0.f;
    g_mlp[t] = 0.f;
    if (t < PLIN) g_pg[t] = 0.f;
    g_g2[t] = 0.f;
}

// fused Q/K/V GEMV: out n in [0,8*hd) -> q; [8hd,9hd) -> k; [9hd,10hd) -> v
// grid (M/64, 4), block 256 (TN=64, TY=4), chunk 256 over e
__global__ void k_qkv(const float* __restrict__ Wq, const float* __restrict__ Wk,
                      const float* __restrict__ Wv, int hd, int lhd) {
    __shared__ float xs[256];
    __shared__ float sred[256];
    int t = threadIdx.x;
    int k0 = blockIdx.y * 256;
    xs[t] = g_hs[k0 + t];
    __syncthreads();
    int tx = t & 63, ty = t >> 6;
    int n = blockIdx.x * 64 + tx;
    int nq = NHD * hd;
    const float* W; int ld; int col;
    if (n < nq)           { W = Wq; ld = 4096; col = ((n >> lhd) << 9) + (n & (hd - 1)); }
    else if (n < nq + hd) { W = Wk; ld = 512;  col = n - nq; }
    else                  { W = Wv; ld = 512;  col = n - nq - hd; }
    const float* wp = W + (size_t)(k0 + ty) * ld + col;
    size_t step = 4 * (size_t)ld;
    float acc = 0.f;
    #pragma unroll 8
    for (int i = 0; i < 64; i++) { acc += xs[ty + 4 * i] * wp[0]; wp += step; }
    sred[t] = acc;
    __syncthreads();
    if (ty == 0) {
        float s = sred[tx] + sred[tx + 64] + sred[tx + 128] + sred[tx + 192];
        atomicAdd(&g_qkv[n], s);
    }
}

// q/k rmsnorm + rope, v norm; also zero downstream accumulators; 1 block x 512
__global__ void k_qkvfin(const float* __restrict__ costab, const float* __restrict__ sintab,
                         const float* __restrict__ qnw, const float* __restrict__ knw,
                         const int* __restrict__ posp, int hd, int lhd, int saveidx) {
    int t = threadIdx.x, lane = t & 31, w = t >> 5;
    __shared__ float sc[10];
    if (w < 10) {
        float s = 0.f;
        for (int d = lane; d < hd; d += 32) { float x = g_qkv[w * hd + d]; s += x * x; }
        #pragma unroll
        for (int o = 16; o; o >>= 1) s += __shfl_down_sync(0xffffffffu, s, o);
        if (lane == 0) sc[w] = rsqrtf(s / (float)hd + 1e-6f);
    }
    __syncthreads();
    int pos = posp[0];
    const float* cr = costab + (size_t)pos * hd;
    const float* sr = sintab + (size_t)pos * hd;
    int half = hd >> 1;
    for (int i = t; i < NHD * hd; i += 512) {
        int hh = i >> lhd, d = i & (hd - 1);
        float qs = sc[hh];
        float x  = g_qkv[hh * hd + d] * qs * (1.f + qnw[d]);
        int pd = (d < half) ? d + half : d - half;
        float px = g_qkv[hh * hd + pd] * qs * (1.f + qnw[pd]);
        float r  = (d < half) ? -px : px;
        g_qf[i] = x * cr[d] + r * sr[d];
    }
    for (int d = t; d < hd; d += 512) {
        float ks = sc[8];
        float x  = g_qkv[8 * hd + d] * ks * (1.f + knw[d]);
        int pd = (d < half) ? d + half : d - half;
        float px = g_qkv[8 * hd + pd] * ks * (1.f + knw[pd]);
        float r  = (d < half) ? -px : px;
        float kf = x * cr[d] + r * sr[d];
        g_kf[d] = kf;
        float vf = g_qkv[9 * hd + d] * sc[9];
        g_vf[d] = vf;
        if (saveidx >= 0) { g_ksave[saveidx][d] = kf; g_vsave[saveidx][d] = vf; }
    }
    for (int i = t; i < NHD * MAXHD; i += 512) g_x[i] = 0.f;
    for (int i = t; i < H; i += 512) { g_o[i] = 0.f; g_mlp[i] = 0.f; g_g2[i] = 0.f; }
    for (int i = t; i < 2 * DFF; i += 512) g_gu[i] = 0.f;
    if (t < PLIN) g_pg[t] = 0.f;
}

// scores[h][t] = q_h . K_t + mask[t];  grid 256, block 256 (8 warps, 1 t each)
__global__ void k_scores(const float* __restrict__ Kc, const float* __restrict__ mask,
                         const int* __restrict__ posp, int hd) {
    __shared__ float sq[NHD * MAXHD];
    int t = threadIdx.x;
    for (int i = t; i < NHD * hd; i += 256) sq[i] = g_qf[i];
    __syncthreads();
    int w = t >> 5, lane = t & 31;
    int tt = blockIdx.x * 8 + w;
    int pos = posp[0];
    const float* kr = (tt == pos) ? g_kf : (Kc + (size_t)tt * MAXHD);
    float acc[NHD];
    #pragma unroll
    for (int hh = 0; hh < NHD; hh++) acc[hh] = 0.f;
    for (int d = lane; d < hd; d += 32) {
        float kv = kr[d];
        #pragma unroll
        for (int hh = 0; hh < NHD; hh++) acc[hh] += kv * sq[hh * hd + d];
    }
    #pragma unroll
    for (int hh = 0; hh < NHD; hh++) {
        float a = acc[hh];
        #pragma unroll
        for (int o = 16; o; o >>= 1) a += __shfl_down_sync(0xffffffffu, a, o);
        if (lane == 0) g_scores[hh * CTX + tt] = a + mask[tt];
    }
}

// per-head softmax; grid 8, block 256
__global__ void k_softmax() {
    int hh = blockIdx.x, t = threadIdx.x;
    float mx = -1e30f;
    for (int i = t; i < CTX; i += 256) mx = fmaxf(mx, g_scores[hh * CTX + i]);
    mx = blockMax(mx);
    float s = 0.f;
    for (int i = t; i < CTX; i += 256) {
        float e = expf(g_scores[hh * CTX + i] - mx);
        g_prob[hh * CTX + i] = e;
        s += e;
    }
    s = blockSum(s);
    float inv = 1.f / s;
    for (int i = t; i < CTX; i += 256) g_prob[hh * CTX + i] *= inv;
}

// attn[h][d] = sum_t p[h][t] V[t][d]; grid (hd/64, 16), block 256 (64 d x 4 t-sub)
__global__ void k_av(const float* __restrict__ Vc, const int* __restrict__ posp, int hd) {
    __shared__ float ps[NHD][128];
    __shared__ float srd[4][512];
    int t = threadIdx.x;
    int t0 = blockIdx.y * 128;
    for (int i = t; i < NHD * 128; i += 256) { int hh = i >> 7, j = i & 127; ps[hh][j] = g_prob[hh * CTX + t0 + j]; }
    __syncthreads();
    int tx = t & 63, ty = t >> 6;
    int d = blockIdx.x * 64 + tx;
    int pos = posp[0];
    float acc[NHD];
    #pragma unroll
    for (int hh = 0; hh < NHD; hh++) acc[hh] = 0.f;
    for (int j = ty; j < 128; j += 4) {
        int tt = t0 + j;
        const float* vr = (tt == pos) ? g_vf : (Vc + (size_t)tt * MAXHD);
        float v = vr[d];
        #pragma unroll
        for (int hh = 0; hh < NHD; hh++) acc[hh] += ps[hh][j] * v;
    }
    #pragma unroll
    for (int hh = 0; hh < NHD; hh++) srd[ty][hh * 64 + tx] = acc[hh];
    __syncthreads();
    if (ty == 0) {
        #pragma unroll
        for (int hh = 0; hh < NHD; hh++) {
            float s = srd[0][hh * 64 + tx] + srd[1][hh * 64 + tx] + srd[2][hh * 64 + tx] + srd[3][hh * 64 + tx];
            atomicAdd(&g_x[hh * hd + d], s);
        }
    }
}

// o[n] = sum over (head,d<hd) attn[h][d] * Wo[h][d][n]; grid (16, 8=heads), block 256
__global__ void k_ogemv(const float* __restrict__ Wo, int hd) {
    __shared__ float xs[MAXHD];
    __shared__ float sred[256];
    int t = threadIdx.x;
    int head = blockIdx.y;
    int k0 = head * hd;
    for (int i = t; i < hd; i += 256) xs[i] = g_x[k0 + i];
    __syncthreads();
    int tx = t & 63, ty = t >> 6;
    int n = blockIdx.x * 64 + tx;
    const float* wp = Wo + ((size_t)(head * MAXHD + ty)) * H + n;
    float acc = 0.f;
    int iters = hd >> 2;
    #pragma unroll 8
    for (int i = 0; i < iters; i++) { acc += xs[ty + 4 * i] * wp[0]; wp += 4 * (size_t)H; }
    sred[t] = acc;
    __syncthreads();
    if (ty == 0) {
        float s = sred[tx] + sred[tx + 64] + sred[tx + 128] + sred[tx + 192];
        atomicAdd(&g_o[n], s);
    }
}

// o rmsnorm + residual; then pre-FF rmsnorm; 1 block x 1024
__global__ void k_finish_o(const float* __restrict__ lnpa, const float* __restrict__ lnpff) {
    int t = threadIdx.x;
    float o = g_o[t];
    float ss = blockSum(o * o);
    float sc = rsqrtf(ss / (float)H + 1e-6f);
    float hv = g_h[t] + o * sc * (1.f + lnpa[t]);
    g_h[t] = hv;
    float ss2 = blockSum(hv * hv);
    float sc2 = rsqrtf(ss2 / (float)H + 1e-6f);
    g_hs[t] = hv * sc2 * (1.f + lnpff[t]);
}

// gate+up GEMV: n<4096 -> Wg, else Wu; grid (128,4), block 256
__global__ void k_gu(const float* __restrict__ Wg, const float* __restrict__ Wu) {
    __shared__ float xs[256];
    __shared__ float sred[256];
    int t = threadIdx.x;
    int k0 = blockIdx.y * 256;
    xs[t] = g_hs[k0 + t];
    __syncthreads();
    int tx = t & 63, ty = t >> 6;
    int n = blockIdx.x * 64 + tx;
    const float* W = (n < DFF) ? Wg : Wu;
    int col = (n < DFF) ? n : n - DFF;
    const float* wp = W + (size_t)(k0 + ty) * DFF + col;
    float acc = 0.f;
    #pragma unroll 8
    for (int i = 0; i < 64; i++) { acc += xs[ty + 4 * i] * wp[0]; wp += 4 * (size_t)DFF; }
    sred[t] = acc;
    __syncthreads();
    if (ty == 0) {
        float s = sred[tx] + sred[tx + 64] + sred[tx + 128] + sred[tx + 192];
        atomicAdd(&g_gu[n], s);
    }
}

// down GEMV with gelu*up prologue; grid (16,16), block 256, chunk 256
__global__ void k_dgemv(const float* __restrict__ Wd) {
    __shared__ float xs[256];
    __shared__ float sred[256];
    int t = threadIdx.x;
    int k0 = blockIdx.y * 256;
    xs[t] = gelu_tanh(g_gu[k0 + t]) * g_gu[DFF + k0 + t];
    __syncthreads();
    int tx = t & 63, ty = t >> 6;
    int n = blockIdx.x * 64 + tx;
    const float* wp = Wd + (size_t)(k0 + ty) * H + n;
    float acc = 0.f;
    #pragma unroll 8
    for (int i = 0; i < 64; i++) { acc += xs[ty + 4 * i] * wp[0]; wp += 4 * (size_t)H; }
    sred[t] = acc;
    __syncthreads();
    if (ty == 0) {
        float s = sred[tx] + sred[tx + 64] + sred[tx + 128] + sred[tx + 192];
        atomicAdd(&g_mlp[n], s);
    }
}

// mlp rmsnorm + residual; 1 block x 1024
__global__ void k_finish_ff(const float* __restrict__ lnpost) {
    int t = threadIdx.x;
    float m = g_mlp[t];
    float ss = blockSum(m * m);
    float sc = rsqrtf(ss / (float)H + 1e-6f);
    g_h[t] = g_h[t] + m * sc * (1.f + lnpost[t]);
}

// per-layer-input gate GEMV: x = h (raw), W [1024,256]; grid (4,8), chunk 128
__global__ void k_pg(const float* __restrict__ Wpg) {
    __shared__ float xs[128];
    __shared__ float sred[256];
    int t = threadIdx.x;
    int k0 = blockIdx.y * 128;
    if (t < 128) xs[t] = g_h[k0 + t];
    __syncthreads();
    int tx = t & 63, ty = t >> 6;
    int n = blockIdx.x * 64 + tx;
    const float* wp = Wpg + (size_t)(k0 + ty) * PLIN + n;
    float acc = 0.f;
    #pragma unroll 8
    for (int i = 0; i < 32; i++) { acc += xs[ty + 4 * i] * wp[0]; wp += 4 * (size_t)PLIN; }
    sred[t] = acc;
    __syncthreads();
    if (ty == 0) {
        float s = sred[tx] + sred[tx + 64] + sred[tx + 128] + sred[tx + 192];
        atomicAdd(&g_pg[n], s);
    }
}

// per-layer-input proj with gelu*pls prologue; grid (16,2), chunk 128
__global__ void k_pp(const float* __restrict__ Wpp, const float* __restrict__ pls) {
    __shared__ float xs[128];
    __shared__ float sred[256];
    int t = threadIdx.x;
    int k0 = blockIdx.y * 128;
    if (t < 128) xs[t] = gelu_tanh(g_pg[k0 + t]) * pls[k0 + t];
    __syncthreads();
    int tx = t & 63, ty = t >> 6;
    int n = blockIdx.x * 64 + tx;
    const float* wp = Wpp + (size_t)(k0 + ty) * H + n;
    float acc = 0.f;
    #pragma unroll 8
    for (int i = 0; i < 32; i++) { acc += xs[ty + 4 * i] * wp[0]; wp += 4 * (size_t)H; }
    sred[t] = acc;
    __syncthreads();
    if (ty == 0) {
        float s = sred[tx] + sred[tx + 64] + sred[tx + 128] + sred[tx + 192];
        atomicAdd(&g_g2[n], s);
    }
}

// pli rmsnorm + residual + layer scalar; fuse next layer's input rmsnorm; 1 block x 1024
__global__ void k_finish_pli(const float* __restrict__ lnppli, const float* __restrict__ scal,
                             const float* __restrict__ lnin_next, float* __restrict__ outp) {
    int t = threadIdx.x;
    float g2 = g_g2[t];
    float ss = blockSum(g2 * g2);
    float sc = rsqrtf(ss / (float)H + 1e-6f);
    float hv = (g_h[t] + g2 * sc * (1.f + lnppli[t])) * scal[0];
    g_h[t] = hv;
    if (outp) outp[t] = hv;
    if (lnin_next) {
        float ss2 = blockSum(hv * hv);
        float sc2 = rsqrtf(ss2 / (float)H + 1e-6f);
        g_hs[t] = hv * sc2 * (1.f + lnin_next[t]);
        for (int i = t; i < 10 * MAXHD; i += 1024) g_qkv[i] = 0.f;
    }
}

// write k13,v13,k14,v14 (cache rows with pos row substituted); grid 3072 x 1024
__global__ void k_kvout(const float* __restrict__ kvc, const int* __restrict__ posp,
                        float* __restrict__ out) {
    int idx = blockIdx.x * 1024 + threadIdx.x;
    int pos = posp[0];
    float val;
    if (idx < 524288) {                                    // k13: [2048,256]
        int tt = idx >> 8, d = idx & 255;
        val = (tt == pos) ? g_ksave[0][d] : kvc[((size_t)13 * CTX + tt) * MAXHD + d];
    } else if (idx < 1048576) {                            // v13
        int i = idx - 524288; int tt = i >> 8, d = i & 255;
        val = (tt == pos) ? g_vsave[0][d] : kvc[((size_t)(NL + 13) * CTX + tt) * MAXHD + d];
    } else if (idx < 2097152) {                            // k14: [2048,512]
        int i = idx - 1048576; int tt = i >> 9, d = i & 511;
        val = (tt == pos) ? g_ksave[1][d] : kvc[((size_t)14 * CTX + tt) * MAXHD + d];
    } else {                                               // v14
        int i = idx - 2097152; int tt = i >> 9, d = i & 511;
        val = (tt == pos) ? g_vsave[1][d] : kvc[((size_t)(NL + 14) * CTX + tt) * MAXHD + d];
    }
    out[1024 + idx] = val;
}

// ---------------- host ----------------
extern "C" void kernel_launch(void* const* d_in, const int* in_sizes, int n_in,
                              void* d_out, int out_size) {
    const float* embed   = (const float*)d_in[0];
    const float* cos_s   = (const float*)d_in[1];
    const float* sin_s   = (const float*)d_in[2];
    const float* cos_f   = (const float*)d_in[3];
    const float* sin_f   = (const float*)d_in[4];
    const float* ln_in   = (const float*)d_in[5];
    const float* ln_pa   = (const float*)d_in[6];
    const float* ln_pff  = (const float*)d_in[7];
    const float* ln_post = (const float*)d_in[8];
    const float* ln_ppli = (const float*)d_in[9];
    const float* qn_w    = (const float*)d_in[10];
    const float* kn_w    = (const float*)d_in[11];
    const float* Wq      = (const float*)d_in[12];
    const float* Wk      = (const float*)d_in[13];
    const float* Wv      = (const float*)d_in[14];
    const float* Wo      = (const float*)d_in[15];
    const float* Wg      = (const float*)d_in[16];
    const float* Wu      = (const float*)d_in[17];
    const float* Wd      = (const float*)d_in[18];
    const float* Wpg     = (const float*)d_in[19];
    const float* Wpp     = (const float*)d_in[20];
    const float* lsc     = (const float*)d_in[21];
    const float* kvc     = (const float*)d_in[22];
    const float* plc     = (const float*)d_in[23];
    const float* img     = (const float*)d_in[24];
    const float* mask    = (const float*)d_in[25];
    // d_in[26] = update_mask (unused; pos used directly)
    const int*   ids     = (const int*)d_in[27];
    const int*   posp    = (const int*)d_in[28];
    float* out = (float*)d_out;

    k_init<<<1, 1024>>>(embed, img, ids, ln_in);

    for (int l = 0; l < NL; l++) {
        bool full = ((l + 1) % 5 == 0);
        int hd  = full ? 512 : 256;
        int lhd = full ? 9 : 8;
        const float* ct = full ? cos_f : cos_s;
        const float* st = full ? sin_f : sin_s;
        size_t lo = (size_t)l;
        const float* Wq_l  = Wq  + lo * H * NHD * MAXHD;
        const float* Wk_l  = Wk  + lo * H * MAXHD;
        const float* Wv_l  = Wv  + lo * H * MAXHD;
        const float* Wo_l  = Wo  + lo * NHD * MAXHD * H;
        const float* Wg_l  = Wg  + lo * H * DFF;
        const float* Wu_l  = Wu  + lo * H * DFF;
        const float* Wd_l  = Wd  + lo * DFF * H;
        const float* Wpg_l = Wpg + lo * H * PLIN;
        const float* Wpp_l = Wpp + lo * PLIN * H;

        int M = 10 * hd;
        k_qkv<<<dim3(M / 64, 4), 256>>>(Wq_l, Wk_l, Wv_l, hd, lhd);
        int sv = (l == 13) ? 0 : ((l == 14) ? 1 : -1);
        k_qkvfin<<<1, 512>>>(ct, st, qn_w + lo * MAXHD, kn_w + lo * MAXHD, posp, hd, lhd, sv);
        k_scores<<<CTX / 8, 256>>>(kvc + lo * CTX * MAXHD, mask, posp, hd);
        k_softmax<<<NHD, 256>>>();
        k_av<<<dim3(hd / 64, 16), 256>>>(kvc + (size_t)(NL + l) * CTX * MAXHD, posp, hd);
        k_ogemv<<<dim3(16, NHD), 256>>>(Wo_l, hd);
        k_finish_o<<<1, 1024>>>(ln_pa + lo * H, ln_pff + lo * H);
        k_gu<<<dim3(128, 4), 256>>>(Wg_l, Wu_l);
        k_dgemv<<<dim3(16, 16), 256>>>(Wd_l);
        k_finish_ff<<<1, 1024>>>(ln_post + lo * H);
        k_pg<<<dim3(4, 8), 256>>>(Wpg_l);
        k_pp<<<dim3(16, 2), 256>>>(Wpp_l, plc + lo * PLIN);
        k_finish_pli<<<1, 1024>>>(ln_ppli + lo * H, lsc + l,
                                  (l < NL - 1) ? (ln_in + (lo + 1) * H) : nullptr,
                                  (l == NL - 1) ? out : nullptr);
    }

    k_kvout<<<3072, 1024>>>(kvc, posp, out);
}

// round 5
// speedup vs baseline: 1.1785x; 1.1785x over previous
#include <cuda_runtime.h>
#include <math.h>

#define H 1024
#define NHD 8
#define DFF 4096
#define PLIN 256
#define CTX 2048
#define MAXHD 512
#define NL 15
#define NBLK 148
#define NTHR 1024

// ---------------- device state (no allocations allowed) ----------------
__device__ float g_hbuf[2][H];            // ping-pong residual stream
__device__ float g_qkv[10 * MAXHD];
__device__ float g_scores[NHD * CTX];
__device__ float g_x[NHD * MAXHD];
__device__ float g_o[H];
__device__ float g_gu[2 * DFF];
__device__ float g_mlp[H];
__device__ float g_pg[PLIN];
__device__ float g_g2[H];
__device__ float g_vf[MAXHD];
__device__ float g_ksave[2][MAXHD];
__device__ float g_vsave[2][MAXHD];
__device__ unsigned g_pmax[NBLK * NHD];
__device__ float g_esum[4 * NHD];
__device__ unsigned g_bar_count;
__device__ volatile unsigned g_bar_gen;

// ---------------- helpers ----------------
__device__ __forceinline__ void gsync() {
    __syncthreads();
    if (threadIdx.x == 0) {
        unsigned gen = g_bar_gen;          // read BEFORE arriving
        __threadfence();
        if (atomicAdd(&g_bar_count, 1u) == NBLK - 1) {
            g_bar_count = 0;
            __threadfence();
            g_bar_gen = gen + 1;
        } else {
            while (g_bar_gen == gen) __nanosleep(32);
            __threadfence();
        }
    }
    __syncthreads();
}

__device__ __forceinline__ float gelu_tanh(float x) {
    float x3 = x * x * x;
    return 0.5f * x * (1.f + tanhf(0.7978845608028654f * (x + 0.044715f * x3)));
}

__device__ __forceinline__ unsigned fenc(float f) {
    unsigned u = __float_as_uint(f);
    return (u & 0x80000000u) ? ~u : (u | 0x80000000u);
}
__device__ __forceinline__ float fdec(unsigned e) {
    unsigned u = (e & 0x80000000u) ? (e & 0x7fffffffu) : ~e;
    return __uint_as_float(u);
}

__device__ float blockSum(float v) {
    __shared__ float red[32];
    int lane = threadIdx.x & 31, wid = threadIdx.x >> 5, nw = blockDim.x >> 5;
    __syncthreads();
    #pragma unroll
    for (int o = 16; o; o >>= 1) v += __shfl_down_sync(0xffffffffu, v, o);
    if (lane == 0) red[wid] = v;
    __syncthreads();
    float s = (threadIdx.x < nw) ? red[threadIdx.x] : 0.f;
    if (wid == 0) {
        #pragma unroll
        for (int o = 16; o; o >>= 1) s += __shfl_down_sync(0xffffffffu, s, o);
        if (lane == 0) red[0] = s;
    }
    __syncthreads();
    return red[0];
}

// ---------------- megakernel ----------------
__global__ void __launch_bounds__(NTHR, 1) megakernel(
    const float* __restrict__ embed, const float* __restrict__ cos_s, const float* __restrict__ sin_s,
    const float* __restrict__ cos_f, const float* __restrict__ sin_f,
    const float* __restrict__ ln_in, const float* __restrict__ ln_pa, const float* __restrict__ ln_pff,
    const float* __restrict__ ln_post, const float* __restrict__ ln_ppli,
    const float* __restrict__ qn_w, const float* __restrict__ kn_w,
    const float* __restrict__ Wq, const float* __restrict__ Wk, const float* __restrict__ Wv,
    const float* __restrict__ Wo, const float* __restrict__ Wg, const float* __restrict__ Wu,
    const float* __restrict__ Wd, const float* __restrict__ Wpg, const float* __restrict__ Wpp,
    const float* __restrict__ lsc, const float* __restrict__ kvc, const float* __restrict__ plc,
    const float* __restrict__ img, const float* __restrict__ mask,
    const int* __restrict__ ids, const int* __restrict__ posp,
    float* __restrict__ out)
{
    const int t = threadIdx.x;
    const int bid = blockIdx.x;
    __shared__ float s_a[4096];
    __shared__ float s_b[1024];
    __shared__ float s_c[1024];
    __shared__ float s_red[1024];
    __shared__ float s_m[16];
    __shared__ unsigned s_bmax[8];

    const int pos = posp[0];
    int cp = 0;  // current g_hbuf parity (tracked identically by all blocks)

    for (int l = 0; l < NL; l++) {
        const bool full = ((l + 1) % 5 == 0);
        const int hd = full ? 512 : 256;
        const int lhd = full ? 9 : 8;
        const float* Wq_l = Wq + (size_t)l * H * NHD * MAXHD;
        const float* Wk_l = Wk + (size_t)l * H * MAXHD;
        const float* Wv_l = Wv + (size_t)l * H * MAXHD;

        // ===== preamble: fold prev finish_pli (or init), compute hs into s_b =====
        {
            float hv;
            if (l == 0) {
                float a = fabsf(img[t]);
                float asum = blockSum(a);
                float is = (asum > 0.f) ? 1.f : 0.f;
                hv = embed[(size_t)ids[0] * H + t] * 32.0f * (1.f - is) + img[t] * is;
            } else {
                float g2 = g_g2[t];
                float ss = blockSum(g2 * g2);
                float sc = rsqrtf(ss / (float)H + 1e-6f);
                hv = (g_hbuf[cp][t] + g2 * sc * (1.f + ln_ppli[(size_t)(l - 1) * H + t])) * lsc[l - 1];
            }
            if (bid == 0) g_hbuf[cp ^ 1][t] = hv;
            float ss2 = blockSum(hv * hv);
            float sc2 = rsqrtf(ss2 / (float)H + 1e-6f);
            s_b[t] = hv * sc2 * (1.f + ln_in[(size_t)l * H + t]);
            __syncthreads();
            cp ^= 1;
        }

        // ===== QKV gemv: N = 10*hd, K = 1024, tile 16, full-K per tile =====
        {
            int nq = NHD * hd, T = (10 * hd) >> 4;
            int tx = t & 15, kl = t >> 4;  // 64 k-lanes
            for (int tile = bid; tile < T; tile += NBLK) {
                int n = tile * 16 + tx;
                const float* W; int ld, col;
                if (n < nq)            { W = Wq_l; ld = NHD * MAXHD; col = ((n >> lhd) << 9) + (n & (hd - 1)); }
                else if (n < nq + hd)  { W = Wk_l; ld = MAXHD;       col = n - nq; }
                else                   { W = Wv_l; ld = MAXHD;       col = n - nq - hd; }
                const float* wp = W + (size_t)kl * ld + col;
                size_t step = (size_t)64 * ld;
                float acc = 0.f;
                #pragma unroll
                for (int i = 0; i < 16; i++) { acc += s_b[kl + 64 * i] * wp[0]; wp += step; }
                s_red[t] = acc; __syncthreads();
                #pragma unroll
                for (int s = 512; s >= 16; s >>= 1) { if (t < s) s_red[t] += s_red[t + s]; __syncthreads(); }
                if (t < 16) g_qkv[tile * 16 + t] = s_red[t];
                __syncthreads();
            }
        }
        gsync();

        // ===== scores (+ rope/rms fold, + per-block max partials) =====
        {
            int w = t >> 5, lane = t & 31;
            if (t < 8) s_bmax[t] = 0u;
            if (w < 10) {
                float s = 0.f;
                for (int d = lane; d < hd; d += 32) { float x = g_qkv[w * hd + d]; s += x * x; }
                #pragma unroll
                for (int o = 16; o; o >>= 1) s += __shfl_down_sync(0xffffffffu, s, o);
                if (lane == 0) s_m[w] = rsqrtf(s / (float)hd + 1e-6f);
            }
            __syncthreads();
            const float* cr = (full ? cos_f : cos_s) + (size_t)pos * hd;
            const float* sr = (full ? sin_f : sin_s) + (size_t)pos * hd;
            const float* qw = qn_w + (size_t)l * MAXHD;
            const float* kw = kn_w + (size_t)l * MAXHD;
            int half = hd >> 1;
            for (int i = t; i < NHD * hd; i += NTHR) {
                int hh = i >> lhd, d = i & (hd - 1);
                float qs = s_m[hh];
                float x  = g_qkv[hh * hd + d] * qs * (1.f + qw[d]);
                int pd = (d < half) ? d + half : d - half;
                float px = g_qkv[hh * hd + pd] * qs * (1.f + qw[pd]);
                float r  = (d < half) ? -px : px;
                s_a[i] = x * cr[d] + r * sr[d];
            }
            for (int d = t; d < hd; d += NTHR) {
                float ks = s_m[8];
                float x  = g_qkv[8 * hd + d] * ks * (1.f + kw[d]);
                int pd = (d < half) ? d + half : d - half;
                float px = g_qkv[8 * hd + pd] * ks * (1.f + kw[pd]);
                float r  = (d < half) ? -px : px;
                float kf = x * cr[d] + r * sr[d];
                s_b[d] = kf;
                float vf = g_qkv[9 * hd + d] * s_m[9];
                s_c[d] = vf;
                if (bid == 0) {
                    g_vf[d] = vf;
                    if (l == 13) { g_ksave[0][d] = kf; g_vsave[0][d] = vf; }
                    if (l == 14) { g_ksave[1][d] = kf; g_vsave[1][d] = vf; }
                }
            }
            if (bid == 2) { for (int i = t; i < NHD * hd; i += NTHR) g_x[i] = 0.f; }
            __syncthreads();

            int gw = bid * 32 + w;
            const float* Kc = kvc + (size_t)l * CTX * MAXHD;
            if (gw < CTX) {
                int tt = gw;
                const float* kr = (tt == pos) ? s_b : (Kc + (size_t)tt * MAXHD);
                float acc[NHD];
                #pragma unroll
                for (int h = 0; h < NHD; h++) acc[h] = 0.f;
                for (int d = lane; d < hd; d += 32) {
                    float kv = kr[d];
                    #pragma unroll
                    for (int h = 0; h < NHD; h++) acc[h] += kv * s_a[h * hd + d];
                }
                #pragma unroll
                for (int h = 0; h < NHD; h++) {
                    float a = acc[h];
                    #pragma unroll
                    for (int o = 16; o; o >>= 1) a += __shfl_down_sync(0xffffffffu, a, o);
                    if (lane == 0) {
                        float v = a + mask[tt];
                        g_scores[h * CTX + tt] = v;
                        atomicMax(&s_bmax[h], fenc(v));
                    }
                }
            }
            __syncthreads();
            if (t < 8) g_pmax[bid * 8 + t] = s_bmax[t];
        }
        gsync();

        // ===== AV (+softmax fold): blocks = (hd/16 d-tiles) x 4 t-segs =====
        {
            int nDT = hd >> 4;
            int nAB = nDT * 4;
            if (t < 8) {
                unsigned mx = 0u;
                for (int b = 0; b < NBLK; b++) mx = max(mx, g_pmax[b * 8 + t]);
                s_m[t] = fdec(mx);
            }
            __syncthreads();
            if (bid < nAB) {
                int dt = bid % nDT, seg = bid / nDT;
                int t0 = seg * 512;
                // phase A: probs chunk into s_a[8][512]
                for (int i = t; i < NHD * 512; i += NTHR) {
                    int h = i >> 9, j = i & 511;
                    s_a[i] = __expf(g_scores[h * CTX + t0 + j] - s_m[h]);
                }
                __syncthreads();
                if (dt == 0) {
                    int w = t >> 5, lane = t & 31;
                    if (w < 8) {
                        float s = 0.f;
                        for (int j = lane; j < 512; j += 32) s += s_a[w * 512 + j];
                        #pragma unroll
                        for (int o = 16; o; o >>= 1) s += __shfl_down_sync(0xffffffffu, s, o);
                        if (lane == 0) g_esum[seg * 8 + w] = s;
                    }
                }
                // phase B: partial AV
                int dl = t & 15, tl = t >> 4;  // 16 d x 64 t-lanes
                int d = dt * 16 + dl;
                const float* Vc = kvc + (size_t)(NL + l) * CTX * MAXHD;
                float acc[NHD];
                #pragma unroll
                for (int h = 0; h < NHD; h++) acc[h] = 0.f;
                for (int j = tl; j < 512; j += 64) {
                    int tt = t0 + j;
                    const float* vr = (tt == pos) ? g_vf : (Vc + (size_t)tt * MAXHD);
                    float v = vr[d];
                    #pragma unroll
                    for (int h = 0; h < NHD; h++) acc[h] += s_a[h * 512 + j] * v;
                }
                #pragma unroll
                for (int h = 0; h < NHD; h++) {
                    __syncthreads();
                    s_red[t] = acc[h];
                    __syncthreads();
                    #pragma unroll
                    for (int s = 512; s >= 16; s >>= 1) { if (t < s) s_red[t] += s_red[t + s]; __syncthreads(); }
                    if (t < 16) atomicAdd(&g_x[h * hd + dt * 16 + t], s_red[t]);
                }
            }
        }
        gsync();

        // ===== O gemv (+normalize preamble): N=1024, K=8*hd, tile 8 =====
        {
            if (t < 8) {
                float s = g_esum[t] + g_esum[8 + t] + g_esum[16 + t] + g_esum[24 + t];
                s_m[t] = 1.f / s;
            }
            __syncthreads();
            for (int i = t; i < NHD * hd; i += NTHR) s_a[i] = g_x[i] * s_m[i >> lhd];
            __syncthreads();
            const float* Wo_l = Wo + (size_t)l * NHD * MAXHD * H;
            int tx = t & 7, kl = t >> 3;  // 128 k-lanes
            int K = NHD * hd;
            for (int tile = bid; tile < 128; tile += NBLK) {
                int n = tile * 8 + tx;
                float acc = 0.f;
                for (int k = kl; k < K; k += 128) {
                    int head = k >> lhd, d = k & (hd - 1);
                    acc += s_a[k] * Wo_l[((size_t)(head * MAXHD + d)) * H + n];
                }
                s_red[t] = acc; __syncthreads();
                #pragma unroll
                for (int s = 512; s >= 8; s >>= 1) { if (t < s) s_red[t] += s_red[t + s]; __syncthreads(); }
                if (t < 8) g_o[tile * 8 + t] = s_red[t];
                __syncthreads();
            }
        }
        gsync();

        // ===== GU gemv (+finish_o fold): N=8192, K=1024, tile 64; gelu at gate store =====
        {
            float o = g_o[t];
            float ss = blockSum(o * o);
            float sc = rsqrtf(ss / (float)H + 1e-6f);
            float hv = g_hbuf[cp][t] + o * sc * (1.f + ln_pa[(size_t)l * H + t]);
            if (bid == 0) g_hbuf[cp ^ 1][t] = hv;
            float ss2 = blockSum(hv * hv);
            float sc2 = rsqrtf(ss2 / (float)H + 1e-6f);
            s_b[t] = hv * sc2 * (1.f + ln_pff[(size_t)l * H + t]);
            __syncthreads();
            const float* Wg_l = Wg + (size_t)l * H * DFF;
            const float* Wu_l = Wu + (size_t)l * H * DFF;
            int tx = t & 63, kl = t >> 6;  // 16 k-lanes
            for (int tile = bid; tile < 128; tile += NBLK) {
                int n = tile * 64 + tx;
                const float* W = (n < DFF) ? Wg_l : Wu_l;
                int col = (n < DFF) ? n : n - DFF;
                const float* wp = W + (size_t)kl * DFF + col;
                float acc = 0.f;
                #pragma unroll 8
                for (int i = 0; i < 64; i++) { acc += s_b[kl + 16 * i] * wp[0]; wp += (size_t)16 * DFF; }
                s_red[t] = acc; __syncthreads();
                #pragma unroll
                for (int s = 512; s >= 64; s >>= 1) { if (t < s) s_red[t] += s_red[t + s]; __syncthreads(); }
                if (t < 64) {
                    float r = s_red[t];
                    int n2 = tile * 64 + t;
                    g_gu[n2] = (n2 < DFF) ? gelu_tanh(r) : r;
                }
                __syncthreads();
            }
            cp ^= 1;
        }
        gsync();

        // ===== down gemv: N=1024, K=4096, tile 8 =====
        {
            for (int i = t; i < DFF; i += NTHR) s_a[i] = g_gu[i] * g_gu[DFF + i];
            __syncthreads();
            const float* Wd_l = Wd + (size_t)l * DFF * H;
            int tx = t & 7, kl = t >> 3;  // 128 k-lanes
            for (int tile = bid; tile < 128; tile += NBLK) {
                int n = tile * 8 + tx;
                const float* wp = Wd_l + (size_t)kl * H + n;
                float acc = 0.f;
                #pragma unroll 8
                for (int i = 0; i < 32; i++) { acc += s_a[kl + 128 * i] * wp[0]; wp += (size_t)128 * H; }
                s_red[t] = acc; __syncthreads();
                #pragma unroll
                for (int s = 512; s >= 8; s >>= 1) { if (t < s) s_red[t] += s_red[t + s]; __syncthreads(); }
                if (t < 8) g_mlp[tile * 8 + t] = s_red[t];
                __syncthreads();
            }
        }
        gsync();

        // ===== PG gemv (+finish_ff fold): N=256, K=1024, tile 4; gelu at store =====
        {
            float m = g_mlp[t];
            float ss = blockSum(m * m);
            float sc = rsqrtf(ss / (float)H + 1e-6f);
            float hv = g_hbuf[cp][t] + m * sc * (1.f + ln_post[(size_t)l * H + t]);
            if (bid == 0) g_hbuf[cp ^ 1][t] = hv;
            s_b[t] = hv;  // raw h input to per-layer gate
            __syncthreads();
            const float* Wpg_l = Wpg + (size_t)l * H * PLIN;
            int tx = t & 3, kl = t >> 2;  // 256 k-lanes
            for (int tile = bid; tile < 64; tile += NBLK) {
                int n = tile * 4 + tx;
                const float* wp = Wpg_l + (size_t)kl * PLIN + n;
                float acc = 0.f;
                #pragma unroll
                for (int i = 0; i < 4; i++) { acc += s_b[kl + 256 * i] * wp[0]; wp += (size_t)256 * PLIN; }
                s_red[t] = acc; __syncthreads();
                #pragma unroll
                for (int s = 512; s >= 4; s >>= 1) { if (t < s) s_red[t] += s_red[t + s]; __syncthreads(); }
                if (t < 4) g_pg[tile * 4 + t] = gelu_tanh(s_red[t]);
                __syncthreads();
            }
            cp ^= 1;
        }
        gsync();

        // ===== PP gemv: N=1024, K=256, tile 8 =====
        {
            const float* pls = plc + (size_t)l * PLIN;
            if (t < PLIN) s_c[t] = g_pg[t] * pls[t];
            __syncthreads();
            const float* Wpp_l = Wpp + (size_t)l * PLIN * H;
            int tx = t & 7, kl = t >> 3;  // 128 k-lanes
            for (int tile = bid; tile < 128; tile += NBLK) {
                int n = tile * 8 + tx;
                const float* wp = Wpp_l + (size_t)kl * H + n;
                float acc = s_c[kl] * wp[0] + s_c[kl + 128] * wp[(size_t)128 * H];
                s_red[t] = acc; __syncthreads();
                #pragma unroll
                for (int s = 512; s >= 8; s >>= 1) { if (t < s) s_red[t] += s_red[t + s]; __syncthreads(); }
                if (t < 8) g_g2[tile * 8 + t] = s_red[t];
                __syncthreads();
            }
        }
        gsync();
    }

    // ===== epilogue: final h (pli fold for layer 14) + KV output copy =====
    if (bid == 0) {
        float g2 = g_g2[t];
        float ss = blockSum(g2 * g2);
        float sc = rsqrtf(ss / (float)H + 1e-6f);
        float hv = (g_hbuf[cp][t] + g2 * sc * (1.f + ln_ppli[(size_t)(NL - 1) * H + t])) * lsc[NL - 1];
        out[t] = hv;
    }
    for (int idx = bid * NTHR + t; idx < 3145728; idx += NBLK * NTHR) {
        float val;
        if (idx < 524288) {                                   // k13: [2048,256]
            int tt = idx >> 8, d = idx & 255;
            val = (tt == pos) ? g_ksave[0][d] : kvc[((size_t)13 * CTX + tt) * MAXHD + d];
        } else if (idx < 1048576) {                           // v13
            int i = idx - 524288; int tt = i >> 8, d = i & 255;
            val = (tt == pos) ? g_vsave[0][d] : kvc[((size_t)(NL + 13) * CTX + tt) * MAXHD + d];
        } else if (idx < 2097152) {                           // k14: [2048,512]
            int i = idx - 1048576; int tt = i >> 9, d = i & 511;
            val = (tt == pos) ? g_ksave[1][d] : kvc[((size_t)14 * CTX + tt) * MAXHD + d];
        } else {                                              // v14
            int i = idx - 2097152; int tt = i >> 9, d = i & 511;
            val = (tt == pos) ? g_vsave[1][d] : kvc[((size_t)(NL + 14) * CTX + tt) * MAXHD + d];
        }
        out[1024 + idx] = val;
    }
}

// ---------------- host ----------------
extern "C" void kernel_launch(void* const* d_in, const int* in_sizes, int n_in,
                              void* d_out, int out_size) {
    megakernel<<<NBLK, NTHR>>>(
        (const float*)d_in[0], (const float*)d_in[1], (const float*)d_in[2],
        (const float*)d_in[3], (const float*)d_in[4], (const float*)d_in[5],
        (const float*)d_in[6], (const float*)d_in[7], (const float*)d_in[8],
        (const float*)d_in[9], (const float*)d_in[10], (const float*)d_in[11],
        (const float*)d_in[12], (const float*)d_in[13], (const float*)d_in[14],
        (const float*)d_in[15], (const float*)d_in[16], (const float*)d_in[17],
        (const float*)d_in[18], (const float*)d_in[19], (const float*)d_in[20],
        (const float*)d_in[21], (const float*)d_in[22], (const float*)d_in[23],
        (const float*)d_in[24], (const float*)d_in[25],
        (const int*)d_in[27], (const int*)d_in[28],
        (float*)d_out);
}

// round 11
// speedup vs baseline: 1.2011x; 1.0192x over previous
#include <cuda_runtime.h>
#include <math.h>

#define H 1024
#define NHD 8
#define DFF 4096
#define PLIN 256
#define CTX 2048
#define MAXHD 512
#define NL 15
#define NBLK 148
#define NTHR 1024

// ---------------- device state ----------------
__device__ float g_hbuf[2][H];
__device__ float g_qkv[10 * MAXHD];
__device__ float g_scores[NHD * CTX];
__device__ float g_x[NHD * MAXHD];
__device__ float g_o[H];
__device__ float g_gu[2 * DFF];
__device__ float g_mlp[H];
__device__ float g_pg[PLIN];
__device__ float g_g2[H];
__device__ float g_vf[MAXHD];
__device__ float g_ksave[2][MAXHD];
__device__ float g_vsave[2][MAXHD];
__device__ unsigned g_pmax[64 * NHD];
__device__ float g_esum[8 * NHD];
__device__ unsigned g_bar_count;
__device__ volatile unsigned g_bar_gen;

// ---------------- helpers ----------------
__device__ __forceinline__ void gsync() {
    __syncthreads();
    if (threadIdx.x == 0) {
        unsigned gen = g_bar_gen;
        __threadfence();
        if (atomicAdd(&g_bar_count, 1u) == NBLK - 1) {
            g_bar_count = 0;
            __threadfence();
            g_bar_gen = gen + 1;
        } else {
            while (g_bar_gen == gen) __nanosleep(20);
            __threadfence();
        }
    }
    __syncthreads();
}

__device__ __forceinline__ float gelu_tanh(float x) {
    float x3 = x * x * x;
    return 0.5f * x * (1.f + tanhf(0.7978845608028654f * (x + 0.044715f * x3)));
}

__device__ __forceinline__ unsigned fenc(float f) {
    unsigned u = __float_as_uint(f);
    return (u & 0x80000000u) ? ~u : (u | 0x80000000u);
}
__device__ __forceinline__ float fdec(unsigned e) {
    unsigned u = (e & 0x80000000u) ? (e & 0x7fffffffu) : ~e;
    return __uint_as_float(u);
}

__device__ float blockSum(float v) {
    __shared__ float red[32];
    int lane = threadIdx.x & 31, wid = threadIdx.x >> 5, nw = blockDim.x >> 5;
    __syncthreads();
    #pragma unroll
    for (int o = 16; o; o >>= 1) v += __shfl_down_sync(0xffffffffu, v, o);
    if (lane == 0) red[wid] = v;
    __syncthreads();
    float s = (threadIdx.x < nw) ? red[threadIdx.x] : 0.f;
    if (wid == 0) {
        #pragma unroll
        for (int o = 16; o; o >>= 1) s += __shfl_down_sync(0xffffffffu, s, o);
        if (lane == 0) red[0] = s;
    }
    __syncthreads();
    return red[0];
}

// ---------------- megakernel ----------------
__global__ void __launch_bounds__(NTHR, 1) megakernel(
    const float* __restrict__ embed, const float* __restrict__ cos_s, const float* __restrict__ sin_s,
    const float* __restrict__ cos_f, const float* __restrict__ sin_f,
    const float* __restrict__ ln_in, const float* __restrict__ ln_pa, const float* __restrict__ ln_pff,
    const float* __restrict__ ln_post, const float* __restrict__ ln_ppli,
    const float* __restrict__ qn_w, const float* __restrict__ kn_w,
    const float* __restrict__ Wq, const float* __restrict__ Wk, const float* __restrict__ Wv,
    const float* __restrict__ Wo, const float* __restrict__ Wg, const float* __restrict__ Wu,
    const float* __restrict__ Wd, const float* __restrict__ Wpg, const float* __restrict__ Wpp,
    const float* __restrict__ lsc, const float* __restrict__ kvc, const float* __restrict__ plc,
    const float* __restrict__ img, const float* __restrict__ mask,
    const int* __restrict__ ids, const int* __restrict__ posp,
    float* __restrict__ out)
{
    const int t = threadIdx.x;
    const int bid = blockIdx.x;
    __shared__ float4 s_a4[1024];     // 4096 floats
    __shared__ float4 s_b4[256];      // 1024 floats
    __shared__ float4 s_c4[256];      // 1024 floats
    __shared__ float4 s_red4[1024];   // reduction
    __shared__ float s_m[16];
    __shared__ unsigned s_bmax[8];
    float* s_a = (float*)s_a4;
    float* s_b = (float*)s_b4;
    float* s_c = (float*)s_c4;

    const int pos = posp[0];
    int cp = 0;

    // ===== init: zero accumulators =====
    if (bid == 0) { for (int i = t; i < 10 * MAXHD; i += NTHR) g_qkv[i] = 0.f; }
    if (bid == 1) { for (int i = t; i < NHD * MAXHD; i += NTHR) g_x[i] = 0.f; }
    if (bid == 2) { g_o[t] = 0.f; g_mlp[t] = 0.f; }
    if (bid == 3) { g_g2[t] = 0.f; if (t < PLIN) g_pg[t] = 0.f; }
    gsync();

    for (int l = 0; l < NL; l++) {
        const bool full = ((l + 1) % 5 == 0);
        const int hd = full ? 512 : 256;
        const int lhd = full ? 9 : 8;
        const float* Wq_l = Wq + (size_t)l * H * NHD * MAXHD;
        const float* Wk_l = Wk + (size_t)l * H * MAXHD;
        const float* Wv_l = Wv + (size_t)l * H * MAXHD;

        // ===== preamble: residual + input rmsnorm into s_b =====
        {
            float hv;
            if (l == 0) {
                float a = fabsf(img[t]);
                float asum = blockSum(a);
                float is = (asum > 0.f) ? 1.f : 0.f;
                hv = embed[(size_t)ids[0] * H + t] * 32.0f * (1.f - is) + img[t] * is;
            } else {
                float g2 = g_g2[t];
                float ss = blockSum(g2 * g2);
                float sc = rsqrtf(ss / (float)H + 1e-6f);
                hv = (g_hbuf[cp][t] + g2 * sc * (1.f + ln_ppli[(size_t)(l - 1) * H + t])) * lsc[l - 1];
            }
            if (bid == 0) g_hbuf[cp ^ 1][t] = hv;
            float ss2 = blockSum(hv * hv);
            float sc2 = rsqrtf(ss2 / (float)H + 1e-6f);
            s_b[t] = hv * sc2 * (1.f + ln_in[(size_t)l * H + t]);
            __syncthreads();
            cp ^= 1;
        }

        // ===== QKV gemv: 64-col tiles x ksplit, float4 =====
        {
            const int tiles = (10 * hd) >> 6;        // 40 or 80
            const int ksp = full ? 2 : 4;
            const int kseg = H / ksp;                // 512 or 256
            const int iters = kseg >> 6;             // 8 or 4
            const int nq = NHD * hd;
            const int tx = t & 15, kl = t >> 4;
            for (int job = bid; job < tiles * ksp; job += NBLK) {
                int tile = job % tiles, ks = job / tiles;
                int n0 = tile << 6;
                const float* W; int ld, col0;
                if (n0 < nq)           { W = Wq_l; ld = NHD * MAXHD; col0 = ((n0 >> lhd) << 9) + (n0 & (hd - 1)); }
                else if (n0 < nq + hd) { W = Wk_l; ld = MAXHD; col0 = n0 - nq; }
                else                   { W = Wv_l; ld = MAXHD; col0 = n0 - nq - hd; }
                int kbase = ks * kseg;
                const float4* wp = (const float4*)W + ((((size_t)(kbase + kl)) * ld + col0) >> 2) + tx;
                size_t step = (size_t)16 * ld;       // float4 units = 64 rows
                float4 acc = make_float4(0.f, 0.f, 0.f, 0.f);
                #pragma unroll 8
                for (int i = 0; i < iters; i++) {
                    float xv = s_b[kbase + kl + (i << 6)];
                    float4 w = *wp; wp += step;
                    acc.x += xv * w.x; acc.y += xv * w.y; acc.z += xv * w.z; acc.w += xv * w.w;
                }
                s_red4[t] = acc; __syncthreads();
                #pragma unroll
                for (int s = 512; s >= 16; s >>= 1) {
                    if (t < s) { float4 a = s_red4[t], b = s_red4[t + s];
                        s_red4[t] = make_float4(a.x + b.x, a.y + b.y, a.z + b.z, a.w + b.w); }
                    __syncthreads();
                }
                if (t < 64) atomicAdd(&g_qkv[n0 + t], ((float*)s_red4)[t]);
                __syncthreads();
            }
        }
        gsync();

        // ===== scores: rope/rms fold + q.K with float4 =====
        {
            int w = t >> 5, lane = t & 31;
            if (bid < 64) {
                if (t < 8) s_bmax[t] = 0u;
                if (w < 10) {
                    float s = 0.f;
                    for (int d = lane; d < hd; d += 32) { float x = g_qkv[w * hd + d]; s += x * x; }
                    #pragma unroll
                    for (int o = 16; o; o >>= 1) s += __shfl_down_sync(0xffffffffu, s, o);
                    if (lane == 0) s_m[w] = rsqrtf(s / (float)hd + 1e-6f);
                }
                __syncthreads();
                const float* cr = (full ? cos_f : cos_s) + (size_t)pos * hd;
                const float* sr = (full ? sin_f : sin_s) + (size_t)pos * hd;
                const float* qw = qn_w + (size_t)l * MAXHD;
                const float* kw = kn_w + (size_t)l * MAXHD;
                int half = hd >> 1;
                for (int i = t; i < NHD * hd; i += NTHR) {
                    int hh = i >> lhd, d = i & (hd - 1);
                    float qs = s_m[hh];
                    float x = g_qkv[hh * hd + d] * qs * (1.f + qw[d]);
                    int pd = (d < half) ? d + half : d - half;
                    float px = g_qkv[hh * hd + pd] * qs * (1.f + qw[pd]);
                    float r = (d < half) ? -px : px;
                    s_a[i] = x * cr[d] + r * sr[d];
                }
                if (t < hd) {
                    int d = t;
                    float ks = s_m[8];
                    float x = g_qkv[8 * hd + d] * ks * (1.f + kw[d]);
                    int pd = (d < half) ? d + half : d - half;
                    float px = g_qkv[8 * hd + pd] * ks * (1.f + kw[pd]);
                    float r = (d < half) ? -px : px;
                    float kf = x * cr[d] + r * sr[d];
                    s_b[d] = kf;
                    float vf = g_qkv[9 * hd + d] * s_m[9];
                    s_c[d] = vf;
                    if (bid == 0) {
                        g_vf[d] = vf;
                        if (l == 13) { g_ksave[0][d] = kf; g_vsave[0][d] = vf; }
                        if (l == 14) { g_ksave[1][d] = kf; g_vsave[1][d] = vf; }
                    }
                }
                __syncthreads();

                int tt = bid * 32 + w;
                const float4* kr = (tt == pos) ? (const float4*)s_b
                                               : (const float4*)(kvc + ((size_t)l * CTX + tt) * MAXHD);
                int np = hd >> 7;   // float4 passes: 2 or 4
                float acc[NHD];
                #pragma unroll
                for (int h = 0; h < NHD; h++) acc[h] = 0.f;
                for (int p = 0; p < np; p++) {
                    float4 kv = kr[lane + (p << 5)];
                    #pragma unroll
                    for (int h = 0; h < NHD; h++) {
                        float4 q = s_a4[((h * hd) >> 2) + lane + (p << 5)];
                        acc[h] += kv.x * q.x + kv.y * q.y + kv.z * q.z + kv.w * q.w;
                    }
                }
                #pragma unroll
                for (int h = 0; h < NHD; h++) {
                    float a = acc[h];
                    #pragma unroll
                    for (int o = 16; o; o >>= 1) a += __shfl_down_sync(0xffffffffu, a, o);
                    if (lane == 0) {
                        float v = a + mask[tt];
                        g_scores[h * CTX + tt] = v;
                        atomicMax(&s_bmax[h], fenc(v));
                    }
                }
                __syncthreads();
                if (t < 8) g_pmax[bid * 8 + t] = s_bmax[t];
            } else if (bid == 64) {
                for (int i = t; i < NHD * MAXHD; i += NTHR) g_x[i] = 0.f;
            }
        }
        gsync();

        // ===== AV (+softmax fold): (hd/128 d-tiles) x 8 t-segs, float2 V =====
        {
            const int nDT = hd >> 7;       // 2 or 4
            const int nAB = nDT * 8;
            if (bid < nAB) {
                if (t < 8) {
                    unsigned mx = 0u;
                    for (int b = 0; b < 64; b++) mx = max(mx, g_pmax[b * 8 + t]);
                    s_m[t] = fdec(mx);
                }
                __syncthreads();
                int dt = bid % nDT, seg = bid / nDT;
                int t0 = seg << 8;
                for (int i = t; i < NHD * 256; i += NTHR) {
                    int h = i >> 8, j = i & 255;
                    s_a[i] = __expf(g_scores[h * CTX + t0 + j] - s_m[h]);
                }
                __syncthreads();
                if (dt == 0) {
                    int w = t >> 5, lane = t & 31;
                    if (w < 8) {
                        float s = 0.f;
                        for (int j = lane; j < 256; j += 32) s += s_a[w * 256 + j];
                        #pragma unroll
                        for (int o = 16; o; o >>= 1) s += __shfl_down_sync(0xffffffffu, s, o);
                        if (lane == 0) g_esum[seg * 8 + w] = s;
                    }
                }
                int dl = t & 63, tl = t >> 6;          // 64 d-lanes (x f2), 16 t-lanes
                int dc2 = (dt << 6) + dl;              // float2 index
                const float* Vc = kvc + (size_t)(NL + l) * CTX * MAXHD;
                float2 acc2[NHD];
                #pragma unroll
                for (int h = 0; h < NHD; h++) acc2[h] = make_float2(0.f, 0.f);
                for (int j = tl; j < 256; j += 16) {
                    int tt = t0 + j;
                    const float2* vr = (tt == pos) ? (const float2*)g_vf
                                                   : (const float2*)(Vc + (size_t)tt * MAXHD);
                    float2 v = vr[dc2];
                    #pragma unroll
                    for (int h = 0; h < NHD; h++) {
                        float p = s_a[(h << 8) + j];
                        acc2[h].x += p * v.x; acc2[h].y += p * v.y;
                    }
                }
                #pragma unroll
                for (int r = 0; r < 4; r++) {
                    __syncthreads();
                    s_red4[t] = make_float4(acc2[2 * r].x, acc2[2 * r].y, acc2[2 * r + 1].x, acc2[2 * r + 1].y);
                    __syncthreads();
                    #pragma unroll
                    for (int s = 512; s >= 64; s >>= 1) {
                        if (t < s) { float4 a = s_red4[t], b = s_red4[t + s];
                            s_red4[t] = make_float4(a.x + b.x, a.y + b.y, a.z + b.z, a.w + b.w); }
                        __syncthreads();
                    }
                    if (t < 64) {
                        float4 v = s_red4[t];
                        int dc = (dt << 7) + (t << 1);
                        atomicAdd(&g_x[(2 * r) * hd + dc], v.x);
                        atomicAdd(&g_x[(2 * r) * hd + dc + 1], v.y);
                        atomicAdd(&g_x[(2 * r + 1) * hd + dc], v.z);
                        atomicAdd(&g_x[(2 * r + 1) * hd + dc + 1], v.w);
                    }
                }
            } else if (bid == nAB) {
                g_o[t] = 0.f;
            }
        }
        gsync();

        // ===== O gemv: N=1024 (16 tiles) x ksplit 8, float4 =====
        {
            if (t < 8) {
                float s = 0.f;
                #pragma unroll
                for (int sg = 0; sg < 8; sg++) s += g_esum[sg * 8 + t];
                s_m[t] = 1.f / s;
            }
            __syncthreads();
            for (int i = t; i < NHD * hd; i += NTHR) s_a[i] = g_x[i] * s_m[i >> lhd];
            __syncthreads();
            const float* Wo_l = Wo + (size_t)l * NHD * MAXHD * H;
            const int K = NHD * hd;
            const int kseg = K >> 3;                  // 256 or 512
            const int iters = kseg >> 6;              // 4 or 8
            const int tx = t & 15, kl = t >> 4;
            for (int job = bid; job < 128; job += NBLK) {
                int tile = job & 15, ks = job >> 4;
                int n0 = tile << 6;
                int kbase = ks * kseg;
                float4 acc = make_float4(0.f, 0.f, 0.f, 0.f);
                #pragma unroll 8
                for (int i = 0; i < iters; i++) {
                    int k = kbase + kl + (i << 6);
                    int head = k >> lhd, d = k & (hd - 1);
                    const float4* wp = (const float4*)Wo_l + (((((size_t)(head * MAXHD + d)) * H) + n0) >> 2) + tx;
                    float xv = s_a[k];
                    float4 w = *wp;
                    acc.x += xv * w.x; acc.y += xv * w.y; acc.z += xv * w.z; acc.w += xv * w.w;
                }
                s_red4[t] = acc; __syncthreads();
                #pragma unroll
                for (int s = 512; s >= 16; s >>= 1) {
                    if (t < s) { float4 a = s_red4[t], b = s_red4[t + s];
                        s_red4[t] = make_float4(a.x + b.x, a.y + b.y, a.z + b.z, a.w + b.w); }
                    __syncthreads();
                }
                if (t < 64) atomicAdd(&g_o[n0 + t], ((float*)s_red4)[t]);
                __syncthreads();
            }
        }
        gsync();

        // ===== GU gemv (+finish_o fold): N=8192, 128 tiles, full K, gelu at gate store =====
        {
            float o = g_o[t];
            float ss = blockSum(o * o);
            float sc = rsqrtf(ss / (float)H + 1e-6f);
            float hv = g_hbuf[cp][t] + o * sc * (1.f + ln_pa[(size_t)l * H + t]);
            if (bid == 0) g_hbuf[cp ^ 1][t] = hv;
            float ss2 = blockSum(hv * hv);
            float sc2 = rsqrtf(ss2 / (float)H + 1e-6f);
            s_b[t] = hv * sc2 * (1.f + ln_pff[(size_t)l * H + t]);
            __syncthreads();
            cp ^= 1;
            const float* Wg_l = Wg + (size_t)l * H * DFF;
            const float* Wu_l = Wu + (size_t)l * H * DFF;
            const int tx = t & 15, kl = t >> 4;
            for (int tile = bid; tile < 128; tile += NBLK) {
                int n0 = tile << 6;
                const float* W = (n0 < DFF) ? Wg_l : Wu_l;
                int col0 = (n0 < DFF) ? n0 : n0 - DFF;
                const float4* wp = (const float4*)W + ((((size_t)kl * DFF) + col0) >> 2) + tx;
                float4 acc = make_float4(0.f, 0.f, 0.f, 0.f);
                #pragma unroll 16
                for (int i = 0; i < 16; i++) {
                    float xv = s_b[kl + (i << 6)];
                    float4 w = *wp; wp += (size_t)16 * DFF;
                    acc.x += xv * w.x; acc.y += xv * w.y; acc.z += xv * w.z; acc.w += xv * w.w;
                }
                s_red4[t] = acc; __syncthreads();
                #pragma unroll
                for (int s = 512; s >= 16; s >>= 1) {
                    if (t < s) { float4 a = s_red4[t], b = s_red4[t + s];
                        s_red4[t] = make_float4(a.x + b.x, a.y + b.y, a.z + b.z, a.w + b.w); }
                    __syncthreads();
                }
                if (t < 64) {
                    int n2 = n0 + t;
                    float r = ((float*)s_red4)[t];
                    g_gu[n2] = (n2 < DFF) ? gelu_tanh(r) : r;
                }
                __syncthreads();
            }
            if (bid == 128) g_mlp[t] = 0.f;
        }
        gsync();

        // ===== down gemv: N=1024 (16 tiles) x ksplit 8 =====
        {
            for (int i = t; i < DFF; i += NTHR) s_a[i] = g_gu[i] * g_gu[DFF + i];
            __syncthreads();
            const float* Wd_l = Wd + (size_t)l * DFF * H;
            const int tx = t & 15, kl = t >> 4;
            for (int job = bid; job < 128; job += NBLK) {
                int tile = job & 15, ks = job >> 4;
                int n0 = tile << 6;
                int kbase = ks << 9;    // 512 per seg
                const float4* wp = (const float4*)Wd_l + (((((size_t)(kbase + kl)) * H) + n0) >> 2) + tx;
                float4 acc = make_float4(0.f, 0.f, 0.f, 0.f);
                #pragma unroll 8
                for (int i = 0; i < 8; i++) {
                    float xv = s_a[kbase + kl + (i << 6)];
                    float4 w = *wp; wp += (size_t)16 * H;
                    acc.x += xv * w.x; acc.y += xv * w.y; acc.z += xv * w.z; acc.w += xv * w.w;
                }
                s_red4[t] = acc; __syncthreads();
                #pragma unroll
                for (int s = 512; s >= 16; s >>= 1) {
                    if (t < s) { float4 a = s_red4[t], b = s_red4[t + s];
                        s_red4[t] = make_float4(a.x + b.x, a.y + b.y, a.z + b.z, a.w + b.w); }
                    __syncthreads();
                }
                if (t < 64) atomicAdd(&g_mlp[n0 + t], ((float*)s_red4)[t]);
                __syncthreads();
            }
            if (bid == 128 && t < PLIN) g_pg[t] = 0.f;
        }
        gsync();

        // ===== PG gemv (+finish_ff fold): N=256 (4 tiles) x ksplit 8 =====
        {
            float m = g_mlp[t];
            float ss = blockSum(m * m);
            float sc = rsqrtf(ss / (float)H + 1e-6f);
            float hv = g_hbuf[cp][t] + m * sc * (1.f + ln_post[(size_t)l * H + t]);
            if (bid == 0) g_hbuf[cp ^ 1][t] = hv;
            s_b[t] = hv;
            __syncthreads();
            cp ^= 1;
            const float* Wpg_l = Wpg + (size_t)l * H * PLIN;
            const int tx = t & 15, kl = t >> 4;
            for (int job = bid; job < 32; job += NBLK) {
                int tile = job & 3, ks = job >> 2;
                int n0 = tile << 6;
                int kbase = ks << 7;   // 128 per seg
                const float4* wp = (const float4*)Wpg_l + (((((size_t)(kbase + kl)) * PLIN) + n0) >> 2) + tx;
                float4 acc = make_float4(0.f, 0.f, 0.f, 0.f);
                #pragma unroll
                for (int i = 0; i < 2; i++) {
                    float xv = s_b[kbase + kl + (i << 6)];
                    float4 w = *wp; wp += (size_t)16 * PLIN;
                    acc.x += xv * w.x; acc.y += xv * w.y; acc.z += xv * w.z; acc.w += xv * w.w;
                }
                s_red4[t] = acc; __syncthreads();
                #pragma unroll
                for (int s = 512; s >= 16; s >>= 1) {
                    if (t < s) { float4 a = s_red4[t], b = s_red4[t + s];
                        s_red4[t] = make_float4(a.x + b.x, a.y + b.y, a.z + b.z, a.w + b.w); }
                    __syncthreads();
                }
                if (t < 64) atomicAdd(&g_pg[n0 + t], ((float*)s_red4)[t]);
                __syncthreads();
            }
            if (bid == 32) g_g2[t] = 0.f;
        }
        gsync();

        // ===== PP gemv: N=1024 (16 tiles) x ksplit 4; gelu applied here =====
        {
            const float* pls = plc + (size_t)l * PLIN;
            if (t < PLIN) s_c[t] = gelu_tanh(g_pg[t]) * pls[t];
            __syncthreads();
            const float* Wpp_l = Wpp + (size_t)l * PLIN * H;
            const int tx = t & 15, kl = t >> 4;
            for (int job = bid; job < 64; job += NBLK) {
                int tile = job & 15, ks = job >> 4;
                int n0 = tile << 6;
                int kbase = ks << 6;   // 64 per seg
                const float4* wp = (const float4*)Wpp_l + (((((size_t)(kbase + kl)) * H) + n0) >> 2) + tx;
                float xv = s_c[kbase + kl];
                float4 w = *wp;
                float4 acc = make_float4(xv * w.x, xv * w.y, xv * w.z, xv * w.w);
                s_red4[t] = acc; __syncthreads();
                #pragma unroll
                for (int s = 512; s >= 16; s >>= 1) {
                    if (t < s) { float4 a = s_red4[t], b = s_red4[t + s];
                        s_red4[t] = make_float4(a.x + b.x, a.y + b.y, a.z + b.z, a.w + b.w); }
                    __syncthreads();
                }
                if (t < 64) atomicAdd(&g_g2[n0 + t], ((float*)s_red4)[t]);
                __syncthreads();
            }
            if (bid == 64) { for (int i = t; i < 10 * MAXHD; i += NTHR) g_qkv[i] = 0.f; }
        }
        gsync();
    }

    // ===== epilogue =====
    if (bid == 0) {
        float g2 = g_g2[t];
        float ss = blockSum(g2 * g2);
        float sc = rsqrtf(ss / (float)H + 1e-6f);
        float hv = (g_hbuf[cp][t] + g2 * sc * (1.f + ln_ppli[(size_t)(NL - 1) * H + t])) * lsc[NL - 1];
        out[t] = hv;
    }
    // KV output copy, float4 (786432 float4s)
    {
        float4* out4 = (float4*)(out + 1024);
        const float4* kvc4 = (const float4*)kvc;
        for (int i = bid * NTHR + t; i < 786432; i += NBLK * NTHR) {
            float4 val;
            if (i < 131072) {                                 // k13 [2048,256]
                int tt = i >> 6, d4 = i & 63;
                val = (tt == pos) ? ((const float4*)g_ksave[0])[d4]
                                  : kvc4[((((size_t)13 * CTX + tt) * MAXHD) >> 2) + d4];
            } else if (i < 262144) {                          // v13
                int j = i - 131072; int tt = j >> 6, d4 = j & 63;
                val = (tt == pos) ? ((const float4*)g_vsave[0])[d4]
                                  : kvc4[((((size_t)(NL + 13) * CTX + tt) * MAXHD) >> 2) + d4];
            } else if (i < 524288) {                          // k14 [2048,512]
                int j = i - 262144; int tt = j >> 7, d4 = j & 127;
                val = (tt == pos) ? ((const float4*)g_ksave[1])[d4]
                                  : kvc4[((((size_t)14 * CTX + tt) * MAXHD) >> 2) + d4];
            } else {                                          // v14
                int j = i - 524288; int tt = j >> 7, d4 = j & 127;
                val = (tt == pos) ? ((const float4*)g_vsave[1])[d4]
                                  : kvc4[((((size_t)(NL + 14) * CTX + tt) * MAXHD) >> 2) + d4];
            }
            out4[i] = val;
        }
    }
}

// ---------------- host ----------------
extern "C" void kernel_launch(void* const* d_in, const int* in_sizes, int n_in,
                              void* d_out, int out_size) {
    megakernel<<<NBLK, NTHR>>>(
        (const float*)d_in[0], (const float*)d_in[1], (const float*)d_in[2],
        (const float*)d_in[3], (const float*)d_in[4], (const float*)d_in[5],
        (const float*)d_in[6], (const float*)d_in[7], (const float*)d_in[8],
        (const float*)d_in[9], (const float*)d_in[10], (const float*)d_in[11],
        (const float*)d_in[12], (const float*)d_in[13], (const float*)d_in[14],
        (const float*)d_in[15], (const float*)d_in[16], (const float*)d_in[17],
        (const float*)d_in[18], (const float*)d_in[19], (const float*)d_in[20],
        (const float*)d_in[21], (const float*)d_in[22], (const float*)d_in[23],
        (const float*)d_in[24], (const float*)d_in[25],
        (const int*)d_in[27], (const int*)d_in[28],
        (float*)d_out);
}

// round 12
// speedup vs baseline: 1.2722x; 1.0592x over previous
#include <cuda_runtime.h>
#include <math.h>

#define H 1024
#define NHD 8
#define DFF 4096
#define PLIN 256
#define CTX 2048
#define MAXHD 512
#define NL 15
#define NBLK 148
#define NTHR 1024

// ---------------- device state ----------------
__device__ float g_hbuf[2][H];
__device__ float g_qkv[10 * MAXHD];
__device__ float g_scores[NHD * CTX];
__device__ float g_x[NHD * MAXHD];
__device__ float g_o[H];
__device__ float g_gu[2 * DFF];
__device__ float g_mlp[H];
__device__ float g_pg[PLIN];
__device__ float g_g2[H];
__device__ float g_vf[MAXHD];
__device__ float g_ksave[2][MAXHD];
__device__ float g_vsave[2][MAXHD];
__device__ unsigned g_pmax[128 * NHD];
__device__ float g_esum[16 * NHD];
__device__ float g_sink;
__device__ unsigned g_bar_count;
__device__ volatile unsigned g_bar_gen;

// ---------------- barrier: arrive / wait split ----------------
__device__ __forceinline__ void bar_arrive(unsigned* sgen) {
    __syncthreads();
    if (threadIdx.x == 0) {
        unsigned gen = g_bar_gen;
        __threadfence();
        if (atomicAdd(&g_bar_count, 1u) == NBLK - 1) {
            g_bar_count = 0;
            __threadfence();
            g_bar_gen = gen + 1;
        }
        *sgen = gen;
    }
    __syncthreads();
}
__device__ __forceinline__ void bar_wait(unsigned* sgen) {
    if (threadIdx.x == 0) {
        unsigned gen = *sgen;
        while (g_bar_gen == gen) {}
        __threadfence();
    }
    __syncthreads();
}

// ---------------- helpers ----------------
__device__ __forceinline__ float gelu_tanh(float x) {
    float x3 = x * x * x;
    return 0.5f * x * (1.f + tanhf(0.7978845608028654f * (x + 0.044715f * x3)));
}
__device__ __forceinline__ unsigned fenc(float f) {
    unsigned u = __float_as_uint(f);
    return (u & 0x80000000u) ? ~u : (u | 0x80000000u);
}
__device__ __forceinline__ float fdec(unsigned e) {
    unsigned u = (e & 0x80000000u) ? (e & 0x7fffffffu) : ~e;
    return __uint_as_float(u);
}
__device__ float blockSum(float v) {
    __shared__ float red[32];
    int lane = threadIdx.x & 31, wid = threadIdx.x >> 5, nw = blockDim.x >> 5;
    __syncthreads();
    #pragma unroll
    for (int o = 16; o; o >>= 1) v += __shfl_down_sync(0xffffffffu, v, o);
    if (lane == 0) red[wid] = v;
    __syncthreads();
    float s = (threadIdx.x < nw) ? red[threadIdx.x] : 0.f;
    if (wid == 0) {
        #pragma unroll
        for (int o = 16; o; o >>= 1) s += __shfl_down_sync(0xffffffffu, s, o);
        if (lane == 0) red[0] = s;
    }
    __syncthreads();
    return red[0];
}
__device__ __forceinline__ void pf_sink(float acc) {
    if (__float_as_uint(acc) == 0xDEADBEEFu) g_sink = acc;
}

// ---------------- megakernel ----------------
__global__ void __launch_bounds__(NTHR, 1) megakernel(
    const float* __restrict__ embed, const float* __restrict__ cos_s, const float* __restrict__ sin_s,
    const float* __restrict__ cos_f, const float* __restrict__ sin_f,
    const float* __restrict__ ln_in, const float* __restrict__ ln_pa, const float* __restrict__ ln_pff,
    const float* __restrict__ ln_post, const float* __restrict__ ln_ppli,
    const float* __restrict__ qn_w, const float* __restrict__ kn_w,
    const float* __restrict__ Wq, const float* __restrict__ Wk, const float* __restrict__ Wv,
    const float* __restrict__ Wo, const float* __restrict__ Wg, const float* __restrict__ Wu,
    const float* __restrict__ Wd, const float* __restrict__ Wpg, const float* __restrict__ Wpp,
    const float* __restrict__ lsc, const float* __restrict__ kvc, const float* __restrict__ plc,
    const float* __restrict__ img, const float* __restrict__ mask,
    const int* __restrict__ ids, const int* __restrict__ posp,
    float* __restrict__ out)
{
    const int t = threadIdx.x;
    const int bid = blockIdx.x;
    __shared__ float4 s_a4[1024];     // 4096 floats
    __shared__ float4 s_b4[256];      // 1024 floats
    __shared__ float4 s_c4[256];      // 1024 floats
    __shared__ float4 s_red4[1024];
    __shared__ float s_m[16];
    __shared__ unsigned s_bmax[8];
    __shared__ unsigned s_gen;
    float* s_a = (float*)s_a4;
    float* s_b = (float*)s_b4;
    float* s_c = (float*)s_c4;

    const int pos = posp[0];
    int cp = 0;

    // ===== init: zero accumulators =====
    if (bid == 0) { for (int i = t; i < 10 * MAXHD; i += NTHR) g_qkv[i] = 0.f; }
    if (bid == 1) { for (int i = t; i < NHD * MAXHD; i += NTHR) g_x[i] = 0.f; }
    if (bid == 2) { g_o[t] = 0.f; g_mlp[t] = 0.f; }
    if (bid == 3) { g_g2[t] = 0.f; if (t < PLIN) g_pg[t] = 0.f; }
    bar_arrive(&s_gen); bar_wait(&s_gen);

    for (int l = 0; l < NL; l++) {
        const bool full = ((l + 1) % 5 == 0);
        const int hd = full ? 512 : 256;
        const int lhd = full ? 9 : 8;
        const float* Wq_l = Wq + (size_t)l * H * NHD * MAXHD;
        const float* Wk_l = Wk + (size_t)l * H * MAXHD;
        const float* Wv_l = Wv + (size_t)l * H * MAXHD;
        const float* Wo_l = Wo + (size_t)l * NHD * MAXHD * H;
        const float* Wg_l = Wg + (size_t)l * H * DFF;
        const float* Wu_l = Wu + (size_t)l * H * DFF;
        const float* Wd_l = Wd + (size_t)l * DFF * H;

        // ===== preamble: residual + input rmsnorm into s_b =====
        {
            float hv;
            if (l == 0) {
                float a = fabsf(img[t]);
                float asum = blockSum(a);
                float is = (asum > 0.f) ? 1.f : 0.f;
                hv = embed[(size_t)ids[0] * H + t] * 32.0f * (1.f - is) + img[t] * is;
            } else {
                float g2 = g_g2[t];
                float ss = blockSum(g2 * g2);
                float sc = rsqrtf(ss / (float)H + 1e-6f);
                hv = (g_hbuf[cp][t] + g2 * sc * (1.f + ln_ppli[(size_t)(l - 1) * H + t])) * lsc[l - 1];
            }
            if (bid == 0) g_hbuf[cp ^ 1][t] = hv;
            float ss2 = blockSum(hv * hv);
            float sc2 = rsqrtf(ss2 / (float)H + 1e-6f);
            s_b[t] = hv * sc2 * (1.f + ln_in[(size_t)l * H + t]);
            __syncthreads();
            cp ^= 1;
        }

        // ===== QKV gemv: 64-col tiles, 80 jobs single wave =====
        {
            const int tiles = (10 * hd) >> 6;        // 40 or 80
            const int ksp = full ? 1 : 2;
            const int kseg = H / ksp;                // 1024 or 512
            const int iters = kseg >> 6;             // 16 or 8
            const int nq = NHD * hd;
            const int tx = t & 15, kl = t >> 4;
            for (int job = bid; job < tiles * ksp; job += NBLK) {
                int tile = job % tiles, ks = job / tiles;
                int n0 = tile << 6;
                const float* W; int ld, col0;
                if (n0 < nq)           { W = Wq_l; ld = NHD * MAXHD; col0 = ((n0 >> lhd) << 9) + (n0 & (hd - 1)); }
                else if (n0 < nq + hd) { W = Wk_l; ld = MAXHD; col0 = n0 - nq; }
                else                   { W = Wv_l; ld = MAXHD; col0 = n0 - nq - hd; }
                int kbase = ks * kseg;
                const float4* wp = (const float4*)W + ((((size_t)(kbase + kl)) * ld + col0) >> 2) + tx;
                size_t step = (size_t)16 * ld;
                float4 acc = make_float4(0.f, 0.f, 0.f, 0.f);
                #pragma unroll 8
                for (int i = 0; i < iters; i++) {
                    float xv = s_b[kbase + kl + (i << 6)];
                    float4 w = *wp; wp += step;
                    acc.x += xv * w.x; acc.y += xv * w.y; acc.z += xv * w.z; acc.w += xv * w.w;
                }
                s_red4[t] = acc; __syncthreads();
                #pragma unroll
                for (int s = 512; s >= 16; s >>= 1) {
                    if (t < s) { float4 a = s_red4[t], b = s_red4[t + s];
                        s_red4[t] = make_float4(a.x + b.x, a.y + b.y, a.z + b.z, a.w + b.w); }
                    __syncthreads();
                }
                if (t < 64) atomicAdd(&g_qkv[n0 + t], ((float*)s_red4)[t]);
                __syncthreads();
            }
        }
        bar_arrive(&s_gen);
        // prefetch Wo used-region into L2 (blocks 80..147; idle QKV blocks start early)
        if (bid >= 80) {
            int slot = bid - 80;
            const float4* Wo4 = (const float4*)Wo_l;
            long used = (long)hd << 11;               // 8*hd*256 f4
            long start = (long)slot * 8192;
            float acc = 0.f;
            for (int i = t; i < 8192; i += NTHR) {
                long u = start + i;
                if (u < used) {
                    int ru = (int)(u >> 8);
                    int head = ru >> lhd, dr = ru & (hd - 1);
                    long f4 = (((long)((head << 9) + dr)) << 8) | (u & 255);
                    float4 v = __ldcg(Wo4 + f4);
                    acc += v.x + v.y + v.z + v.w;
                }
            }
            pf_sink(acc);
        }
        bar_wait(&s_gen);

        // ===== scores: 128 blocks x 16 rows; rope/rms fold =====
        {
            int w2 = t >> 5, lane = t & 31;
            if (bid < 128) {
                if (t < 8) s_bmax[t] = 0u;
                if (w2 < 10) {
                    float s = 0.f;
                    for (int d = lane; d < hd; d += 32) { float x = g_qkv[w2 * hd + d]; s += x * x; }
                    #pragma unroll
                    for (int o = 16; o; o >>= 1) s += __shfl_down_sync(0xffffffffu, s, o);
                    if (lane == 0) s_m[w2] = rsqrtf(s / (float)hd + 1e-6f);
                }
                __syncthreads();
                const float* cr = (full ? cos_f : cos_s) + (size_t)pos * hd;
                const float* sr = (full ? sin_f : sin_s) + (size_t)pos * hd;
                const float* qw = qn_w + (size_t)l * MAXHD;
                const float* kw = kn_w + (size_t)l * MAXHD;
                int half = hd >> 1;
                for (int i = t; i < NHD * hd; i += NTHR) {
                    int hh = i >> lhd, d = i & (hd - 1);
                    float qs = s_m[hh];
                    float x = g_qkv[hh * hd + d] * qs * (1.f + qw[d]);
                    int pd = (d < half) ? d + half : d - half;
                    float px = g_qkv[hh * hd + pd] * qs * (1.f + qw[pd]);
                    float r = (d < half) ? -px : px;
                    s_a[i] = x * cr[d] + r * sr[d];
                }
                if (t < hd) {
                    int d = t;
                    float ks = s_m[8];
                    float x = g_qkv[8 * hd + d] * ks * (1.f + kw[d]);
                    int pd = (d < half) ? d + half : d - half;
                    float px = g_qkv[8 * hd + pd] * ks * (1.f + kw[pd]);
                    float r = (d < half) ? -px : px;
                    float kf = x * cr[d] + r * sr[d];
                    s_b[d] = kf;
                    float vf = g_qkv[9 * hd + d] * s_m[9];
                    s_c[d] = vf;
                    if (bid == 0) {
                        g_vf[d] = vf;
                        if (l == 13) { g_ksave[0][d] = kf; g_vsave[0][d] = vf; }
                        if (l == 14) { g_ksave[1][d] = kf; g_vsave[1][d] = vf; }
                    }
                }
                __syncthreads();

                if (w2 < 16) {
                    int tt = bid * 16 + w2;
                    const float4* kr = (tt == pos) ? (const float4*)s_b
                                                   : (const float4*)(kvc + ((size_t)l * CTX + tt) * MAXHD);
                    int np = hd >> 7;
                    float acc[NHD];
                    #pragma unroll
                    for (int h = 0; h < NHD; h++) acc[h] = 0.f;
                    for (int p = 0; p < np; p++) {
                        float4 kv = kr[lane + (p << 5)];
                        #pragma unroll
                        for (int h = 0; h < NHD; h++) {
                            float4 q = s_a4[((h * hd) >> 2) + lane + (p << 5)];
                            acc[h] += kv.x * q.x + kv.y * q.y + kv.z * q.z + kv.w * q.w;
                        }
                    }
                    #pragma unroll
                    for (int h = 0; h < NHD; h++) {
                        float a = acc[h];
                        #pragma unroll
                        for (int o = 16; o; o >>= 1) a += __shfl_down_sync(0xffffffffu, a, o);
                        if (lane == 0) {
                            float v = a + mask[tt];
                            g_scores[h * CTX + tt] = v;
                            atomicMax(&s_bmax[h], fenc(v));
                        }
                    }
                }
                __syncthreads();
                if (t < 8) g_pmax[bid * 8 + t] = s_bmax[t];
            } else if (bid == 128) {
                for (int i = t; i < NHD * MAXHD; i += NTHR) g_x[i] = 0.f;
            }
        }
        bar_arrive(&s_gen);
        // prefetch Wg||Wu into L2 (blocks 64..147)
        if (bid >= 64) {
            int slot = bid - 64;                       // 0..83
            const float4* Wg4 = (const float4*)Wg_l;
            const float4* Wu4 = (const float4*)Wu_l;
            long start = (long)slot * 16384;
            float acc = 0.f;
            for (int i = t; i < 16384; i += NTHR) {
                long u = start + i;
                if (u < 2097152) {
                    float4 v = (u < 1048576) ? __ldcg(Wg4 + u) : __ldcg(Wu4 + (u - 1048576));
                    acc += v.x + v.y + v.z + v.w;
                }
            }
            pf_sink(acc);
        }
        bar_wait(&s_gen);

        // ===== AV (+softmax fold): (hd/128 d-tiles) x 16 t-segs =====
        {
            const int nDT = hd >> 7;       // 2 or 4
            const int nAB = nDT * 16;      // 32 or 64
            if (bid < nAB) {
                if (t < 8) {
                    unsigned mx = 0u;
                    for (int b = 0; b < 128; b++) mx = max(mx, g_pmax[b * 8 + t]);
                    s_m[t] = fdec(mx);
                }
                __syncthreads();
                int dt = bid % nDT, seg = bid / nDT;
                int t0 = seg << 7;                     // 128 per seg
                for (int i = t; i < NHD * 128; i += NTHR) {
                    int h = i >> 7, j = i & 127;
                    s_a[i] = __expf(g_scores[h * CTX + t0 + j] - s_m[h]);
                }
                __syncthreads();
                if (dt == 0) {
                    int w = t >> 5, lane = t & 31;
                    if (w < 8) {
                        float s = 0.f;
                        for (int j = lane; j < 128; j += 32) s += s_a[w * 128 + j];
                        #pragma unroll
                        for (int o = 16; o; o >>= 1) s += __shfl_down_sync(0xffffffffu, s, o);
                        if (lane == 0) g_esum[seg * 8 + w] = s;
                    }
                }
                int dl = t & 63, tl = t >> 6;          // 64 f2-lanes x 16 t-lanes
                int dc2 = (dt << 6) + dl;
                const float* Vc = kvc + (size_t)(NL + l) * CTX * MAXHD;
                float2 acc2[NHD];
                #pragma unroll
                for (int h = 0; h < NHD; h++) acc2[h] = make_float2(0.f, 0.f);
                for (int j = tl; j < 128; j += 16) {
                    int tt = t0 + j;
                    const float2* vr = (tt == pos) ? (const float2*)g_vf
                                                   : (const float2*)(Vc + (size_t)tt * MAXHD);
                    float2 v = vr[dc2];
                    #pragma unroll
                    for (int h = 0; h < NHD; h++) {
                        float p = s_a[(h << 7) + j];
                        acc2[h].x += p * v.x; acc2[h].y += p * v.y;
                    }
                }
                #pragma unroll
                for (int r = 0; r < 4; r++) {
                    __syncthreads();
                    s_red4[t] = make_float4(acc2[2 * r].x, acc2[2 * r].y, acc2[2 * r + 1].x, acc2[2 * r + 1].y);
                    __syncthreads();
                    #pragma unroll
                    for (int s = 512; s >= 64; s >>= 1) {
                        if (t < s) { float4 a = s_red4[t], b = s_red4[t + s];
                            s_red4[t] = make_float4(a.x + b.x, a.y + b.y, a.z + b.z, a.w + b.w); }
                        __syncthreads();
                    }
                    if (t < 64) {
                        float4 v = s_red4[t];
                        int dc = (dt << 7) + (t << 1);
                        atomicAdd(&g_x[(2 * r) * hd + dc], v.x);
                        atomicAdd(&g_x[(2 * r) * hd + dc + 1], v.y);
                        atomicAdd(&g_x[(2 * r + 1) * hd + dc], v.z);
                        atomicAdd(&g_x[(2 * r + 1) * hd + dc + 1], v.w);
                    }
                }
            } else if (bid == nAB) {
                g_o[t] = 0.f;
            }
        }
        bar_arrive(&s_gen);
        // continue Wg||Wu prefetch (blocks 128..147)
        if (bid >= 128) {
            int slot = 84 + (bid - 128);
            const float4* Wg4 = (const float4*)Wg_l;
            const float4* Wu4 = (const float4*)Wu_l;
            long start = (long)slot * 16384;
            float acc = 0.f;
            for (int i = t; i < 16384; i += NTHR) {
                long u = start + i;
                if (u < 2097152) {
                    float4 v = (u < 1048576) ? __ldcg(Wg4 + u) : __ldcg(Wu4 + (u - 1048576));
                    acc += v.x + v.y + v.z + v.w;
                }
            }
            pf_sink(acc);
        }
        bar_wait(&s_gen);

        // ===== O gemv: N=1024 (16 tiles) x ksplit 8 =====
        {
            if (t < 8) {
                float s = 0.f;
                #pragma unroll
                for (int sg = 0; sg < 16; sg++) s += g_esum[sg * 8 + t];
                s_m[t] = 1.f / s;
            }
            __syncthreads();
            for (int i = t; i < NHD * hd; i += NTHR) s_a[i] = g_x[i] * s_m[i >> lhd];
            __syncthreads();
            const int K = NHD * hd;
            const int kseg = K >> 3;
            const int iters = kseg >> 6;
            const int tx = t & 15, kl = t >> 4;
            for (int job = bid; job < 128; job += NBLK) {
                int tile = job & 15, ks = job >> 4;
                int n0 = tile << 6;
                int kbase = ks * kseg;
                float4 acc = make_float4(0.f, 0.f, 0.f, 0.f);
                #pragma unroll 8
                for (int i = 0; i < iters; i++) {
                    int k = kbase + kl + (i << 6);
                    int head = k >> lhd, d = k & (hd - 1);
                    const float4* wp = (const float4*)Wo_l + (((((size_t)(head * MAXHD + d)) * H) + n0) >> 2) + tx;
                    float xv = s_a[k];
                    float4 w = *wp;
                    acc.x += xv * w.x; acc.y += xv * w.y; acc.z += xv * w.z; acc.w += xv * w.w;
                }
                s_red4[t] = acc; __syncthreads();
                #pragma unroll
                for (int s = 512; s >= 16; s >>= 1) {
                    if (t < s) { float4 a = s_red4[t], b = s_red4[t + s];
                        s_red4[t] = make_float4(a.x + b.x, a.y + b.y, a.z + b.z, a.w + b.w); }
                    __syncthreads();
                }
                if (t < 64) atomicAdd(&g_o[n0 + t], ((float*)s_red4)[t]);
                __syncthreads();
            }
        }
        bar_arrive(&s_gen);
        // Wd prefetch part 1 (blocks 128..147)
        if (bid >= 128) {
            int slot = bid - 128;
            const float4* Wd4 = (const float4*)Wd_l;
            long start = (long)slot * 16384;
            float acc = 0.f;
            for (int i = t; i < 16384; i += NTHR) {
                long u = start + i;
                if (u < 1048576) { float4 v = __ldcg(Wd4 + u); acc += v.x + v.y + v.z + v.w; }
            }
            pf_sink(acc);
        }
        bar_wait(&s_gen);

        // ===== GU gemv (+finish_o fold) =====
        {
            float o = g_o[t];
            float ss = blockSum(o * o);
            float sc = rsqrtf(ss / (float)H + 1e-6f);
            float hv = g_hbuf[cp][t] + o * sc * (1.f + ln_pa[(size_t)l * H + t]);
            if (bid == 0) g_hbuf[cp ^ 1][t] = hv;
            float ss2 = blockSum(hv * hv);
            float sc2 = rsqrtf(ss2 / (float)H + 1e-6f);
            s_b[t] = hv * sc2 * (1.f + ln_pff[(size_t)l * H + t]);
            __syncthreads();
            cp ^= 1;
            const int tx = t & 15, kl = t >> 4;
            for (int tile = bid; tile < 128; tile += NBLK) {
                int n0 = tile << 6;
                const float* W = (n0 < DFF) ? Wg_l : Wu_l;
                int col0 = (n0 < DFF) ? n0 : n0 - DFF;
                const float4* wp = (const float4*)W + ((((size_t)kl * DFF) + col0) >> 2) + tx;
                float4 acc = make_float4(0.f, 0.f, 0.f, 0.f);
                #pragma unroll 16
                for (int i = 0; i < 16; i++) {
                    float xv = s_b[kl + (i << 6)];
                    float4 w = *wp; wp += (size_t)16 * DFF;
                    acc.x += xv * w.x; acc.y += xv * w.y; acc.z += xv * w.z; acc.w += xv * w.w;
                }
                s_red4[t] = acc; __syncthreads();
                #pragma unroll
                for (int s = 512; s >= 16; s >>= 1) {
                    if (t < s) { float4 a = s_red4[t], b = s_red4[t + s];
                        s_red4[t] = make_float4(a.x + b.x, a.y + b.y, a.z + b.z, a.w + b.w); }
                    __syncthreads();
                }
                if (t < 64) {
                    int n2 = n0 + t;
                    float r = ((float*)s_red4)[t];
                    g_gu[n2] = (n2 < DFF) ? gelu_tanh(r) : r;
                }
                __syncthreads();
            }
            if (bid == 128) g_mlp[t] = 0.f;
        }
        bar_arrive(&s_gen);
        // Wd prefetch part 2 (blocks 128..147)
        if (bid >= 128) {
            int slot = 20 + (bid - 128);
            const float4* Wd4 = (const float4*)Wd_l;
            long start = (long)slot * 16384;
            float acc = 0.f;
            for (int i = t; i < 16384; i += NTHR) {
                long u = start + i;
                if (u < 1048576) { float4 v = __ldcg(Wd4 + u); acc += v.x + v.y + v.z + v.w; }
            }
            pf_sink(acc);
        }
        bar_wait(&s_gen);

        // ===== down gemv: N=1024 (16 tiles) x ksplit 8 =====
        {
            for (int i = t; i < DFF; i += NTHR) s_a[i] = g_gu[i] * g_gu[DFF + i];
            __syncthreads();
            const int tx = t & 15, kl = t >> 4;
            for (int job = bid; job < 128; job += NBLK) {
                int tile = job & 15, ks = job >> 4;
                int n0 = tile << 6;
                int kbase = ks << 9;
                const float4* wp = (const float4*)Wd_l + (((((size_t)(kbase + kl)) * H) + n0) >> 2) + tx;
                float4 acc = make_float4(0.f, 0.f, 0.f, 0.f);
                #pragma unroll 8
                for (int i = 0; i < 8; i++) {
                    float xv = s_a[kbase + kl + (i << 6)];
                    float4 w = *wp; wp += (size_t)16 * H;
                    acc.x += xv * w.x; acc.y += xv * w.y; acc.z += xv * w.z; acc.w += xv * w.w;
                }
                s_red4[t] = acc; __syncthreads();
                #pragma unroll
                for (int s = 512; s >= 16; s >>= 1) {
                    if (t < s) { float4 a = s_red4[t], b = s_red4[t + s];
                        s_red4[t] = make_float4(a.x + b.x, a.y + b.y, a.z + b.z, a.w + b.w); }
                    __syncthreads();
                }
                if (t < 64) atomicAdd(&g_mlp[n0 + t], ((float*)s_red4)[t]);
                __syncthreads();
            }
            if (bid == 128 && t < PLIN) g_pg[t] = 0.f;
        }
        bar_arrive(&s_gen);
        // prefetch next-layer Wq/Wk/Wv used regions (blocks >= 32)
        if (l + 1 < NL) {
            const int ln = l + 1;
            const bool fn = ((ln + 1) % 5 == 0);
            const int hdn = fn ? 512 : 256;
            const int lhdn = fn ? 9 : 8;
            const long wq_used = (long)2048 * hdn;          // f4 count
            const int wqslots = (int)(wq_used >> 14);       // 32 or 64
            const int kvslots = (256 * hdn) >> 14;          // 4 or 8
            const float4* Wq4n = (const float4*)(Wq + (size_t)ln * H * NHD * MAXHD);
            const float4* Wk4n = (const float4*)(Wk + (size_t)ln * H * MAXHD);
            const float4* Wv4n = (const float4*)(Wv + (size_t)ln * H * MAXHD);
            float acc = 0.f;
            if (bid >= 32 && bid < 32 + wqslots) {
                long start = (long)(bid - 32) * 16384;
                for (int i = t; i < 16384; i += NTHR) {
                    long u = start + i;
                    int e = (int)(u >> (lhdn + 1));
                    int r = (int)(u & ((hdn << 1) - 1));
                    int head = r >> (lhdn - 2);
                    int dd = r & ((hdn >> 2) - 1);
                    float4 v = __ldcg(Wq4n + (long)e * 1024 + head * 128 + dd);
                    acc += v.x + v.y + v.z + v.w;
                }
            } else if (bid >= 32 + wqslots && bid < 32 + wqslots + 2 * kvslots) {
                int s2 = bid - 32 - wqslots;
                const float4* Wb = (s2 < kvslots) ? Wk4n : Wv4n;
                long start = (long)(s2 % kvslots) * 16384;
                for (int i = t; i < 16384; i += NTHR) {
                    long u = start + i;
                    int row = (int)(u >> (lhdn - 2));
                    int c = (int)(u & ((hdn >> 2) - 1));
                    float4 v = __ldcg(Wb + (long)row * 128 + c);
                    acc += v.x + v.y + v.z + v.w;
                }
            }
            pf_sink(acc);
        }
        bar_wait(&s_gen);

        // ===== PG gemv (+finish_ff fold): N=256 (4 tiles) x ksplit 8 =====
        {
            float m = g_mlp[t];
            float ss = blockSum(m * m);
            float sc = rsqrtf(ss / (float)H + 1e-6f);
            float hv = g_hbuf[cp][t] + m * sc * (1.f + ln_post[(size_t)l * H + t]);
            if (bid == 0) g_hbuf[cp ^ 1][t] = hv;
            s_b[t] = hv;
            __syncthreads();
            cp ^= 1;
            const float* Wpg_l = Wpg + (size_t)l * H * PLIN;
            const int tx = t & 15, kl = t >> 4;
            for (int job = bid; job < 32; job += NBLK) {
                int tile = job & 3, ks = job >> 2;
                int n0 = tile << 6;
                int kbase = ks << 7;
                const float4* wp = (const float4*)Wpg_l + (((((size_t)(kbase + kl)) * PLIN) + n0) >> 2) + tx;
                float4 acc = make_float4(0.f, 0.f, 0.f, 0.f);
                #pragma unroll
                for (int i = 0; i < 2; i++) {
                    float xv = s_b[kbase + kl + (i << 6)];
                    float4 w = *wp; wp += (size_t)16 * PLIN;
                    acc.x += xv * w.x; acc.y += xv * w.y; acc.z += xv * w.z; acc.w += xv * w.w;
                }
                s_red4[t] = acc; __syncthreads();
                #pragma unroll
                for (int s = 512; s >= 16; s >>= 1) {
                    if (t < s) { float4 a = s_red4[t], b = s_red4[t + s];
                        s_red4[t] = make_float4(a.x + b.x, a.y + b.y, a.z + b.z, a.w + b.w); }
                    __syncthreads();
                }
                if (t < 64) atomicAdd(&g_pg[n0 + t], ((float*)s_red4)[t]);
                __syncthreads();
            }
            if (bid == 32) g_g2[t] = 0.f;
        }
        bar_arrive(&s_gen); bar_wait(&s_gen);

        // ===== PP gemv: N=1024 (16 tiles) x ksplit 4 =====
        {
            const float* pls = plc + (size_t)l * PLIN;
            if (t < PLIN) s_c[t] = gelu_tanh(g_pg[t]) * pls[t];
            __syncthreads();
            const float* Wpp_l = Wpp + (size_t)l * PLIN * H;
            const int tx = t & 15, kl = t >> 4;
            for (int job = bid; job < 64; job += NBLK) {
                int tile = job & 15, ks = job >> 4;
                int n0 = tile << 6;
                int kbase = ks << 6;
                const float4* wp = (const float4*)Wpp_l + (((((size_t)(kbase + kl)) * H) + n0) >> 2) + tx;
                float xv = s_c[kbase + kl];
                float4 w = *wp;
                float4 acc = make_float4(xv * w.x, xv * w.y, xv * w.z, xv * w.w);
                s_red4[t] = acc; __syncthreads();
                #pragma unroll
                for (int s = 512; s >= 16; s >>= 1) {
                    if (t < s) { float4 a = s_red4[t], b = s_red4[t + s];
                        s_red4[t] = make_float4(a.x + b.x, a.y + b.y, a.z + b.z, a.w + b.w); }
                    __syncthreads();
                }
                if (t < 64) atomicAdd(&g_g2[n0 + t], ((float*)s_red4)[t]);
                __syncthreads();
            }
            if (bid == 64) { for (int i = t; i < 10 * MAXHD; i += NTHR) g_qkv[i] = 0.f; }
        }
        bar_arrive(&s_gen); bar_wait(&s_gen);
    }

    // ===== epilogue =====
    if (bid == 0) {
        float g2 = g_g2[t];
        float ss = blockSum(g2 * g2);
        float sc = rsqrtf(ss / (float)H + 1e-6f);
        float hv = (g_hbuf[cp][t] + g2 * sc * (1.f + ln_ppli[(size_t)(NL - 1) * H + t])) * lsc[NL - 1];
        out[t] = hv;
    }
    {
        float4* out4 = (float4*)(out + 1024);
        const float4* kvc4 = (const float4*)kvc;
        for (int i = bid * NTHR + t; i < 786432; i += NBLK * NTHR) {
            float4 val;
            if (i < 131072) {
                int tt = i >> 6, d4 = i & 63;
                val = (tt == pos) ? ((const float4*)g_ksave[0])[d4]
                                  : kvc4[((((size_t)13 * CTX + tt) * MAXHD) >> 2) + d4];
            } else if (i < 262144) {
                int j = i - 131072; int tt = j >> 6, d4 = j & 63;
                val = (tt == pos) ? ((const float4*)g_vsave[0])[d4]
                                  : kvc4[((((size_t)(NL + 13) * CTX + tt) * MAXHD) >> 2) + d4];
            } else if (i < 524288) {
                int j = i - 262144; int tt = j >> 7, d4 = j & 127;
                val = (tt == pos) ? ((const float4*)g_ksave[1])[d4]
                                  : kvc4[((((size_t)14 * CTX + tt) * MAXHD) >> 2) + d4];
            } else {
                int j = i - 524288; int tt = j >> 7, d4 = j & 127;
                val = (tt == pos) ? ((const float4*)g_vsave[1])[d4]
                                  : kvc4[((((size_t)(NL + 14) * CTX + tt) * MAXHD) >> 2) + d4];
            }
            out4[i] = val;
        }
    }
}

// ---------------- host ----------------
extern "C" void kernel_launch(void* const* d_in, const int* in_sizes, int n_in,
                              void* d_out, int out_size) {
    megakernel<<<NBLK, NTHR>>>(
        (const float*)d_in[0], (const float*)d_in[1], (const float*)d_in[2],
        (const float*)d_in[3], (const float*)d_in[4], (const float*)d_in[5],
        (const float*)d_in[6], (const float*)d_in[7], (const float*)d_in[8],
        (const float*)d_in[9], (const float*)d_in[10], (const float*)d_in[11],
        (const float*)d_in[12], (const float*)d_in[13], (const float*)d_in[14],
        (const float*)d_in[15], (const float*)d_in[16], (const float*)d_in[17],
        (const float*)d_in[18], (const float*)d_in[19], (const float*)d_in[20],
        (const float*)d_in[21], (const float*)d_in[22], (const float*)d_in[23],
        (const float*)d_in[24], (const float*)d_in[25],
        (const int*)d_in[27], (const int*)d_in[28],
        (float*)d_out);
}